// round 9
// baseline (speedup 1.0000x reference)
#include <cuda_runtime.h>
#include <cuda_fp16.h>
#include <math.h>
#include <stdint.h>

#define NN 100000
#define EE 300000
#define DD 256
#define FDIM 512
#define LL 5
#define GG 4000
#define NUM_BOND_C 2
#define BN_EPS 1e-5f
#define MPAD_N 100096   // 782*128
#define MPAD_G 4096     // 32*128

// ---------------- scratch (device globals: no allocation allowed) ----------------
__device__ float g_h[(size_t)NN * DD];
__device__ float g_agg[(size_t)NN * DD];
__device__ float g_tmp[(size_t)NN * FDIM];
__device__ float g_stat[2 * FDIM];
__device__ float g_ab[2 * DD];
__device__ float g_ssum[(size_t)GG * FDIM];
__device__ float g_cnt[GG];
__device__ float g_gfeat[(size_t)GG * FDIM];
__device__ float g_hid[(size_t)GG * (FDIM / 2)];
// fp16 hi/lo fragment buffer for GEMM1 -> GEMM2 intermediate (K=512 operand)
__device__ uint4 g_a16b[(size_t)(MPAD_N / 16) * (FDIM / 16) * 64];
// B16 chunk = (8 cols x 16 k): 32 uint4 = [lane32][hi0,hi1,lo0,lo1]
// offsets (uint4): w1[l]@l*32768 | w2[l]@163840+l*32768 | feat@327680 | head@360448
__device__ uint4 g_w16[393216];

__device__ __forceinline__ float softplus_f(float x) {
    return fmaxf(x, 0.0f) + log1pf(expf(-fabsf(x)));
}

__device__ __forceinline__ void red_add_v4(float* p, float x, float y, float z, float w) {
    asm volatile("red.global.add.v4.f32 [%0], {%1,%2,%3,%4};"
                 :: "l"(p), "f"(x), "f"(y), "f"(z), "f"(w) : "memory");
}
__device__ __forceinline__ void red_add_f32(float* p, float v) {
    asm volatile("red.global.add.f32 [%0], %1;" :: "l"(p), "f"(v) : "memory");
}

// ---------------- fp16 split helpers ----------------
__device__ __forceinline__ void packhl(float x, float y, uint32_t& hi, uint32_t& lo) {
    __half2 h = __floats2half2_rn(x, y);             // low half = x
    float2 hf = __half22float2(h);
    __half2 l = __floats2half2_rn(x - hf.x, y - hf.y);
    hi = *reinterpret_cast<uint32_t*>(&h);
    lo = *reinterpret_cast<uint32_t*>(&l);
}

__device__ __forceinline__ void mma16(float* c, const uint32_t* a, uint32_t b0, uint32_t b1) {
    asm volatile(
        "mma.sync.aligned.m16n8k16.row.col.f32.f16.f16.f32 "
        "{%0,%1,%2,%3},{%4,%5,%6,%7},{%8,%9},{%0,%1,%2,%3};"
        : "+f"(c[0]), "+f"(c[1]), "+f"(c[2]), "+f"(c[3])
        : "r"(a[0]), "r"(a[1]), "r"(a[2]), "r"(a[3]), "r"(b0), "r"(b1));
}

__device__ __forceinline__ void cpa16f(void* dst, const void* src) {
    uint32_t d = (uint32_t)__cvta_generic_to_shared(dst);
    asm volatile("cp.async.cg.shared.global [%0], [%1], 16;" :: "r"(d), "l"(src) : "memory");
}
__device__ __forceinline__ void cp_commit() {
    asm volatile("cp.async.commit_group;" ::: "memory");
}
__device__ __forceinline__ void cp_wait0() {
    asm volatile("cp.async.wait_group 0;" ::: "memory");
}

// ---------------- B16 converter (one warp per (8-col, 16-k) chunk; W is [K,N]) ------
__global__ void conv_b16(const float* __restrict__ W, uint4* __restrict__ dst, int K, int N) {
    int Q = K >> 4;
    int wid = blockIdx.x * (blockDim.x >> 5) + (threadIdx.x >> 5);
    int nch = (N >> 3) * Q;
    if (wid >= nch) return;
    int bn = wid / Q, q = wid - bn * Q;
    int lane = threadIdx.x & 31, g = lane >> 2, t = lane & 3;
    int n = bn * 8 + g;
    int k0 = q * 16 + 2 * t, k1 = k0 + 8;
    uint4 v;
    uint32_t l0, l1;
    packhl(W[(size_t)k0 * N + n], W[(size_t)(k0 + 1) * N + n], v.x, l0);
    packhl(W[(size_t)k1 * N + n], W[(size_t)(k1 + 1) * N + n], v.y, l1);
    v.z = l0;
    v.w = l1;
    dst[(size_t)wid * 32 + lane] = v;
}

// ---------------- fp16x3 tensor-core GEMM ----------------
// A: either fragment-format [Mpad,K] (A16) or fp32 row-major (Afp, converted in-kernel).
// B16 fragment-format [Nc, K]. 128x128 CTA tile, BK=32, 2-stage, 8 warps (4x2).
// outputs: C fp32 (opt), O16 fragment-format (opt), BN stats (opt).
#define GEMM_SMEM_BYTES 65536

__global__ __launch_bounds__(256, 2)
void gemm_f16(const uint4* __restrict__ A16, const float* __restrict__ Afp,
              const uint4* __restrict__ B16, const float* __restrict__ bias,
              float* __restrict__ C, uint4* __restrict__ O16, int M, int Qa, int Nc,
              int act, float* __restrict__ stat, int Qout) {
    extern __shared__ uint4 sm4[];
    const int tid = threadIdx.x, lane = tid & 31, w = tid >> 5;
    const int g = lane >> 2, t = lane & 3;
    const int wm = (w >> 1) * 32, wn = (w & 1) * 64;
    const int brow = blockIdx.y * 128, bcol = blockIdx.x * 128;
    const bool a32 = (Afp != nullptr);
    const int K = Qa << 4;

    // ---- frag-A cp.async descriptors ----
    const uint4* asrc[4];
    uint4* adst[4];
    const uint4* bsrc[4];
    uint4* bdst[4];
#pragma unroll
    for (int j = 0; j < 4; j++) {
        int u = tid + j * 256;
        {
            int chunk = u >> 6, wd = u & 63;
            int bm = chunk >> 1, ql = chunk & 1;
            asrc[j] = A16 + ((size_t)((brow >> 4) + bm) * Qa + ql) * 64 + wd;
            adst[j] = sm4 + (ql * 8 + bm) * 64 + wd;
        }
        {
            int chunk = u >> 5, wd = u & 31;
            int bn = chunk >> 1, ql = chunk & 1;
            bsrc[j] = B16 + ((size_t)((bcol >> 3) + bn) * Qa + ql) * 32 + wd;
            bdst[j] = sm4 + 1024 + (ql * 16 + bn) * 32 + wd;
        }
    }

    // ---- fp32-A mode: warp w owns chunks (bm=w, ql=0/1); rows fixed, col varies with s
    const int a_r0 = brow + w * 16 + g;
    const int a_r1 = a_r0 + 8;
    const bool ok0 = a32 && (a_r0 < M);
    const bool ok1 = a32 && (a_r1 < M);
    const float* Ar0 = Afp + (size_t)(ok0 ? a_r0 : 0) * K;
    const float* Ar1 = Afp + (size_t)(ok1 ? a_r1 : 0) * K;
    float2 fr[2][4];  // [ql][f00,f10,f01,f11]

#define LDA32(s_)                                                               \
    do {                                                                        \
        const float2 z_ = make_float2(0.f, 0.f);                                \
        _Pragma("unroll") for (int ql = 0; ql < 2; ql++) {                      \
            int k_ = ((s_) << 5) + ql * 16 + 2 * t;                             \
            fr[ql][0] = ok0 ? *(const float2*)(Ar0 + k_) : z_;                  \
            fr[ql][1] = ok1 ? *(const float2*)(Ar1 + k_) : z_;                  \
            fr[ql][2] = ok0 ? *(const float2*)(Ar0 + k_ + 8) : z_;              \
            fr[ql][3] = ok1 ? *(const float2*)(Ar1 + k_ + 8) : z_;              \
        }                                                                       \
    } while (0)

#define STA32(buf_)                                                             \
    do {                                                                        \
        _Pragma("unroll") for (int ql = 0; ql < 2; ql++) {                      \
            uint4 hi_, lo_;                                                     \
            packhl(fr[ql][0].x, fr[ql][0].y, hi_.x, lo_.x);                     \
            packhl(fr[ql][1].x, fr[ql][1].y, hi_.y, lo_.y);                     \
            packhl(fr[ql][2].x, fr[ql][2].y, hi_.z, lo_.z);                     \
            packhl(fr[ql][3].x, fr[ql][3].y, hi_.w, lo_.w);                     \
            uint4* p_ = sm4 + (buf_) * 2048 + (ql * 8 + w) * 64 + lane;         \
            p_[0] = hi_;                                                        \
            p_[32] = lo_;                                                       \
        }                                                                       \
    } while (0)

    float acc[2][8][4];
#pragma unroll
    for (int mt = 0; mt < 2; mt++)
#pragma unroll
        for (int nt = 0; nt < 8; nt++)
#pragma unroll
            for (int q = 0; q < 4; q++) acc[mt][nt][q] = 0.0f;

    const int S = Qa >> 1;

    // prologue: stage 0
    if (a32) {
        LDA32(0);
        STA32(0);
    } else {
#pragma unroll
        for (int j = 0; j < 4; j++) cpa16f(adst[j], asrc[j]);
    }
#pragma unroll
    for (int j = 0; j < 4; j++) cpa16f(bdst[j], bsrc[j]);
    cp_commit();

    for (int s = 0; s < S; s++) {
        const int st = s & 1;
        cp_wait0();
        __syncthreads();
        if (s + 1 < S) {
            const int st2 = st ^ 1;
            if (a32) {
                LDA32(s + 1);
            } else {
#pragma unroll
                for (int j = 0; j < 4; j++)
                    cpa16f(adst[j] + st2 * 2048, asrc[j] + (size_t)(s + 1) * 128);
            }
#pragma unroll
            for (int j = 0; j < 4; j++)
                cpa16f(bdst[j] + st2 * 2048, bsrc[j] + (size_t)(s + 1) * 64);
        }
        cp_commit();

#pragma unroll
        for (int ql = 0; ql < 2; ql++) {
            uint4 ah[2], al[2];
#pragma unroll
            for (int mt = 0; mt < 2; mt++) {
                const uint4* ap = sm4 + st * 2048 + (ql * 8 + (wm >> 4) + mt) * 64;
                ah[mt] = ap[lane];
                al[mt] = ap[32 + lane];
            }
#pragma unroll
            for (int nt = 0; nt < 8; nt++) {
                uint4 bv = sm4[st * 2048 + 1024 + (ql * 16 + (wn >> 3) + nt) * 32 + lane];
#pragma unroll
                for (int mt = 0; mt < 2; mt++) {
                    mma16(acc[mt][nt], (const uint32_t*)&ah[mt], bv.x, bv.y);
                    mma16(acc[mt][nt], (const uint32_t*)&ah[mt], bv.z, bv.w);
                    mma16(acc[mt][nt], (const uint32_t*)&al[mt], bv.x, bv.y);
                }
            }
        }

        if (a32 && s + 1 < S) STA32(st ^ 1);
    }

    // ---------------- epilogue ----------------
    const bool do_stats = (stat != nullptr);
    float csum[16], csq[16];
    if (do_stats) {
#pragma unroll
        for (int i = 0; i < 16; i++) { csum[i] = 0.f; csq[i] = 0.f; }
    }

#pragma unroll
    for (int mt = 0; mt < 2; mt++) {
        const int r0 = brow + wm + mt * 16 + g;
        const int r1 = r0 + 8;
#pragma unroll
        for (int j = 0; j < 4; j++) {
            float v[2][4];
#pragma unroll
            for (int e = 0; e < 2; e++) {
                const int nt = j * 2 + e;
                const int col = bcol + wn + nt * 8 + t * 2;
                const float b0 = bias[col];
                const float b1 = bias[col + 1];
                float x0 = acc[mt][nt][0] + b0;
                float x1 = acc[mt][nt][1] + b1;
                float x2 = acc[mt][nt][2] + b0;
                float x3 = acc[mt][nt][3] + b1;
                if (act) {
                    x0 = softplus_f(x0); x1 = softplus_f(x1);
                    x2 = softplus_f(x2); x3 = softplus_f(x3);
                }
                if (r0 >= M) { x0 = 0.f; x1 = 0.f; }
                if (r1 >= M) { x2 = 0.f; x3 = 0.f; }
                v[e][0] = x0; v[e][1] = x1; v[e][2] = x2; v[e][3] = x3;
                if (C) {
                    if (r0 < M) *(float2*)&C[(size_t)r0 * Nc + col] = make_float2(x0, x1);
                    if (r1 < M) *(float2*)&C[(size_t)r1 * Nc + col] = make_float2(x2, x3);
                }
                if (do_stats) {
                    csum[nt * 2] += x0 + x2;
                    csq[nt * 2] += x0 * x0 + x2 * x2;
                    csum[nt * 2 + 1] += x1 + x3;
                    csq[nt * 2 + 1] += x1 * x1 + x3 * x3;
                }
            }
            if (O16) {
                uint4 hi, lo;
                packhl(v[0][0], v[0][1], hi.x, lo.x);
                packhl(v[0][2], v[0][3], hi.y, lo.y);
                packhl(v[1][0], v[1][1], hi.z, lo.z);
                packhl(v[1][2], v[1][3], hi.w, lo.w);
                size_t chunk = (size_t)((brow + wm + mt * 16) >> 4) * Qout +
                               ((bcol + wn) >> 4) + j;
                O16[chunk * 64 + lane] = hi;
                O16[chunk * 64 + 32 + lane] = lo;
            }
        }
    }

    if (do_stats) {
#pragma unroll
        for (int i = 0; i < 16; i++) {
            float sv = csum[i], qv = csq[i];
            sv += __shfl_xor_sync(0xffffffffu, sv, 4);
            sv += __shfl_xor_sync(0xffffffffu, sv, 8);
            sv += __shfl_xor_sync(0xffffffffu, sv, 16);
            qv += __shfl_xor_sync(0xffffffffu, qv, 4);
            qv += __shfl_xor_sync(0xffffffffu, qv, 8);
            qv += __shfl_xor_sync(0xffffffffu, qv, 16);
            if (g == 0) {
                const int col = bcol + wn + (i >> 1) * 8 + t * 2 + (i & 1);
                red_add_f32(&stat[col], sv);
                red_add_f32(&stat[Nc + col], qv);
            }
        }
    }
}

// ---------------- non-GEMM kernels ----------------
__global__ void init_h_kernel(const int* __restrict__ atomics,
                              const float* __restrict__ pos,
                              const float* __restrict__ emb1,
                              const float* __restrict__ w2,
                              const float* __restrict__ b2,
                              float* __restrict__ h) {
    size_t idx = (size_t)blockIdx.x * blockDim.x + threadIdx.x;
    if (idx >= (size_t)NN * DD) return;
    int i = (int)(idx / DD);
    int d = (int)(idx & (DD - 1));
    float p0 = pos[i * 3 + 0], p1 = pos[i * 3 + 1], p2 = pos[i * 3 + 2];
    float v = emb1[(size_t)atomics[i] * DD + d];
    v += p0 * w2[d] + p1 * w2[DD + d] + p2 * w2[2 * DD + d] + b2[d];
    h[idx] = v;
}

__global__ void agg_init_kernel(const float* __restrict__ h,
                                const float* __restrict__ emb_self,
                                float* __restrict__ agg) {
    size_t idx = (size_t)blockIdx.x * blockDim.x + threadIdx.x;
    if (idx >= (size_t)NN * DD / 4) return;
    int d4 = (int)(idx & (DD / 4 - 1)) * 4;
    float4 hv = *((const float4*)h + idx);
    float4 ev = *(const float4*)(emb_self + d4);
    *((float4*)agg + idx) = make_float4(hv.x + ev.x, hv.y + ev.y, hv.z + ev.z, hv.w + ev.w);
}

__global__ void scatter_edges_kernel(const float* __restrict__ h,
                                     const int* __restrict__ edge_index,
                                     const int* __restrict__ edge_attr,
                                     const float* __restrict__ emb,
                                     float* __restrict__ agg) {
    int e = blockIdx.x * (blockDim.x >> 5) + (threadIdx.x >> 5);
    if (e >= EE) return;
    int lane = threadIdx.x & 31;
    int s = edge_index[e];
    int t = edge_index[EE + e];
    const float* hs = h + (size_t)s * DD;
    const float* eb = emb + (size_t)edge_attr[e] * DD;
    float* ag = agg + (size_t)t * DD;
#pragma unroll
    for (int half = 0; half < 2; half++) {
        int c = lane * 4 + half * 128;
        float4 hv = *(const float4*)(hs + c);
        float4 ev = *(const float4*)(eb + c);
        red_add_v4(ag + c, hv.x + ev.x, hv.y + ev.y, hv.z + ev.z, hv.w + ev.w);
    }
}

__global__ void zero_kernel(float* __restrict__ p, size_t n) {
    size_t idx = (size_t)blockIdx.x * blockDim.x + threadIdx.x;
    if (idx < n) p[idx] = 0.0f;
}

__global__ void bn_finalize_kernel(const float* __restrict__ stat,
                                   const float* __restrict__ gamma,
                                   const float* __restrict__ beta,
                                   float* __restrict__ ab) {
    int d = threadIdx.x;
    float mean = stat[d] * (1.0f / NN);
    float var = stat[DD + d] * (1.0f / NN) - mean * mean;
    float inv = rsqrtf(var + BN_EPS);
    float a = gamma[d] * inv;
    ab[d] = a;
    ab[DD + d] = beta[d] - mean * a;
}

__global__ void bn_apply_agg_kernel(float* __restrict__ h, const float* __restrict__ ab,
                                    const float* __restrict__ emb_next,
                                    float* __restrict__ agg, int act) {
    size_t idx = (size_t)blockIdx.x * blockDim.x + threadIdx.x;
    if (idx >= (size_t)NN * DD / 4) return;
    int d4 = (int)(idx & (DD / 4 - 1)) * 4;
    float4 v = *((float4*)h + idx);
    float4 a = *(const float4*)(ab + d4);
    float4 b = *(const float4*)(ab + DD + d4);
    v.x = v.x * a.x + b.x;
    v.y = v.y * a.y + b.y;
    v.z = v.z * a.z + b.z;
    v.w = v.w * a.w + b.w;
    if (act) {
        v.x = softplus_f(v.x);
        v.y = softplus_f(v.y);
        v.z = softplus_f(v.z);
        v.w = softplus_f(v.w);
    }
    *((float4*)h + idx) = v;
    if (agg) {
        float4 e = *(const float4*)(emb_next + d4);
        *((float4*)agg + idx) = make_float4(v.x + e.x, v.y + e.y, v.z + e.z, v.w + e.w);
    }
}

__global__ void pool_count_kernel(const int* __restrict__ batch, float* __restrict__ cnt) {
    int i = blockIdx.x * blockDim.x + threadIdx.x;
    if (i >= NN) return;
    atomicAdd(&cnt[batch[i]], 1.0f);
}

__global__ void pool_sum_kernel(const float* __restrict__ feat,
                                const int* __restrict__ batch,
                                float* __restrict__ ssum) {
    size_t idx = (size_t)blockIdx.x * blockDim.x + threadIdx.x;
    const int CH = FDIM / 4;
    const size_t nchunks = (NN + 7) / 8;
    if (idx >= nchunks * CH) return;
    int f4 = (int)(idx & (CH - 1)) * 4;
    int i0 = (int)(idx / CH) * 8;
    int cur = batch[i0];
    float4 acc = make_float4(0.f, 0.f, 0.f, 0.f);
#pragma unroll
    for (int r = 0; r < 8; r++) {
        int i = i0 + r;
        if (i >= NN) break;
        int b = batch[i];
        if (b != cur) {
            red_add_v4(&ssum[(size_t)cur * FDIM + f4], acc.x, acc.y, acc.z, acc.w);
            acc = make_float4(0.f, 0.f, 0.f, 0.f);
            cur = b;
        }
        float4 v = *(const float4*)(feat + (size_t)i * FDIM + f4);
        acc.x += v.x; acc.y += v.y; acc.z += v.z; acc.w += v.w;
    }
    red_add_v4(&ssum[(size_t)cur * FDIM + f4], acc.x, acc.y, acc.z, acc.w);
}

__global__ void gfeat_kernel(const float* __restrict__ ssum, const float* __restrict__ cnt,
                             float* __restrict__ gfeat) {
    size_t idx = (size_t)blockIdx.x * blockDim.x + threadIdx.x;
    if (idx >= (size_t)GG * FDIM) return;
    int g = (int)(idx / FDIM);
    gfeat[idx] = ssum[idx] / fmaxf(cnt[g], 1.0f);
}

__global__ void head_out_kernel(const float* __restrict__ hid, const float* __restrict__ w2,
                                const float* __restrict__ b2, float* __restrict__ out) {
    int g = blockIdx.x * (blockDim.x >> 5) + (threadIdx.x >> 5);
    if (g >= GG) return;
    int lane = threadIdx.x & 31;
    const float* hr = hid + (size_t)g * (FDIM / 2);
    float s = 0.f;
#pragma unroll
    for (int k = lane; k < FDIM / 2; k += 32) s += hr[k] * w2[k];
#pragma unroll
    for (int o = 16; o; o >>= 1) s += __shfl_down_sync(0xffffffffu, s, o);
    if (lane == 0) out[g] = s + b2[0];
}

// ---------------- host launch ----------------
static inline void launch_gemm(const uint4* A16, const float* Afp, const uint4* B16,
                               const float* bias, float* C, uint4* O16, int M, int Mpad,
                               int Qa, int Nc, int act, float* stat, int Qout) {
    dim3 grid(Nc / 128, Mpad / 128);
    gemm_f16<<<grid, 256, GEMM_SMEM_BYTES>>>(A16, Afp, B16, bias, C, O16, M, Qa, Nc, act,
                                             stat, Qout);
}

extern "C" void kernel_launch(void* const* d_in, const int* in_sizes, int n_in,
                              void* d_out, int out_size) {
    const int* atomics = (const int*)d_in[0];
    const float* pos = (const float*)d_in[1];
    const int* edge_index = (const int*)d_in[2];
    const int* edge_attr = (const int*)d_in[3];
    const int* batch = (const int*)d_in[4];
    const float* x_emb1 = (const float*)d_in[5];
    const float* x_emb2_w = (const float*)d_in[6];
    const float* x_emb2_b = (const float*)d_in[7];
    const float* edge_emb = (const float*)d_in[8];
    const float* mlp_w1 = (const float*)d_in[9];
    const float* mlp_b1 = (const float*)d_in[10];
    const float* mlp_w2 = (const float*)d_in[11];
    const float* mlp_b2 = (const float*)d_in[12];
    const float* bn_gamma = (const float*)d_in[13];
    const float* bn_beta = (const float*)d_in[14];
    const float* feat_w = (const float*)d_in[15];
    const float* feat_b = (const float*)d_in[16];
    const float* head_w1 = (const float*)d_in[17];
    const float* head_b1 = (const float*)d_in[18];
    const float* head_w2 = (const float*)d_in[19];
    const float* head_b2 = (const float*)d_in[20];
    float* out = (float*)d_out;

    float *h, *agg, *tmp, *stat, *ab, *ssum, *cnt, *gfeat, *hid;
    uint4 *a16b, *w16;
    cudaGetSymbolAddress((void**)&h, g_h);
    cudaGetSymbolAddress((void**)&agg, g_agg);
    cudaGetSymbolAddress((void**)&tmp, g_tmp);
    cudaGetSymbolAddress((void**)&stat, g_stat);
    cudaGetSymbolAddress((void**)&ab, g_ab);
    cudaGetSymbolAddress((void**)&ssum, g_ssum);
    cudaGetSymbolAddress((void**)&cnt, g_cnt);
    cudaGetSymbolAddress((void**)&gfeat, g_gfeat);
    cudaGetSymbolAddress((void**)&hid, g_hid);
    cudaGetSymbolAddress((void**)&a16b, g_a16b);
    cudaGetSymbolAddress((void**)&w16, g_w16);

    cudaFuncSetAttribute(gemm_f16, cudaFuncAttributeMaxDynamicSharedMemorySize,
                         GEMM_SMEM_BYTES);

    const size_t ND = (size_t)NN * DD;
    const size_t ND4 = ND / 4;
    const int EL = 256;

    // ---- B16 prep ----
    for (int l = 0; l < LL; l++) {
        conv_b16<<<128, 256>>>(mlp_w1 + (size_t)l * DD * 2 * DD, w16 + l * 32768, DD, 2 * DD);
        conv_b16<<<128, 256>>>(mlp_w2 + (size_t)l * 2 * DD * DD, w16 + 163840 + l * 32768,
                               2 * DD, DD);
    }
    conv_b16<<<128, 256>>>(feat_w, w16 + 327680, DD, FDIM);
    conv_b16<<<128, 256>>>(head_w1, w16 + 360448, FDIM, FDIM / 2);

    init_h_kernel<<<(unsigned)((ND + EL - 1) / EL), EL>>>(atomics, pos, x_emb1, x_emb2_w,
                                                          x_emb2_b, h);
    {
        const float* emb_self0 =
            edge_emb + (size_t)0 * NUM_BOND_C * DD + (size_t)(NUM_BOND_C - 1) * DD;
        agg_init_kernel<<<(unsigned)((ND4 + EL - 1) / EL), EL>>>(h, emb_self0, agg);
    }

    for (int l = 0; l < LL; l++) {
        const float* emb_l = edge_emb + (size_t)l * NUM_BOND_C * DD;

        scatter_edges_kernel<<<(EE + 7) / 8, 256>>>(h, edge_index, edge_attr, emb_l, agg);

        // tmp16 = softplus(agg @ W1 + b1)  [N,512] fragment format (fp32 A converted in-kernel)
        launch_gemm(nullptr, agg, w16 + l * 32768, mlp_b1 + (size_t)l * 2 * DD, nullptr,
                    a16b, NN, MPAD_N, DD / 16, 2 * DD, 1, nullptr, FDIM / 16);

        zero_kernel<<<1, 512>>>(stat, 2 * DD);
        // h = tmp16 @ W2 + b2 (+BN stats)  [N,256] fp32
        launch_gemm(a16b, nullptr, w16 + 163840 + l * 32768, mlp_b2 + (size_t)l * DD, h,
                    nullptr, NN, MPAD_N, FDIM / 16, DD, 0, stat, 1);

        bn_finalize_kernel<<<1, 256>>>(stat, bn_gamma + (size_t)l * DD,
                                       bn_beta + (size_t)l * DD, ab);

        if (l < LL - 1) {
            const float* emb_self_next =
                edge_emb + (size_t)(l + 1) * NUM_BOND_C * DD + (size_t)(NUM_BOND_C - 1) * DD;
            bn_apply_agg_kernel<<<(unsigned)((ND4 + EL - 1) / EL), EL>>>(h, ab, emb_self_next,
                                                                         agg, 1);
        } else {
            bn_apply_agg_kernel<<<(unsigned)((ND4 + EL - 1) / EL), EL>>>(h, ab, nullptr,
                                                                         nullptr, 0);
        }
    }

    // feat = h @ feat_w + feat_b -> tmp fp32
    launch_gemm(nullptr, h, w16 + 327680, feat_b, tmp, nullptr, NN, MPAD_N, DD / 16, FDIM,
                0, nullptr, 1);

    // global mean pool
    zero_kernel<<<(unsigned)(((size_t)GG * FDIM + EL - 1) / EL), EL>>>(ssum, (size_t)GG * FDIM);
    zero_kernel<<<(GG + EL - 1) / EL, EL>>>(cnt, GG);
    pool_count_kernel<<<(NN + EL - 1) / EL, EL>>>(batch, cnt);
    {
        size_t total = ((NN + 7) / 8) * (size_t)(FDIM / 4);
        pool_sum_kernel<<<(unsigned)((total + EL - 1) / EL), EL>>>(tmp, batch, ssum);
    }
    gfeat_kernel<<<(unsigned)(((size_t)GG * FDIM + EL - 1) / EL), EL>>>(ssum, cnt, gfeat);

    // head: hid = softplus(gfeat @ head_w1 + head_b1)
    launch_gemm(nullptr, gfeat, w16 + 360448, head_b1, hid, nullptr, GG, MPAD_G, FDIM / 16,
                FDIM / 2, 1, nullptr, 1);
    head_out_kernel<<<(GG + 7) / 8, 256>>>(hid, head_w2, head_b2, out);
}

// round 10
// speedup vs baseline: 1.0607x; 1.0607x over previous
#include <cuda_runtime.h>
#include <cuda_fp16.h>
#include <math.h>
#include <stdint.h>

#define NN 100000
#define EE 300000
#define DD 256
#define FDIM 512
#define LL 5
#define GG 4000
#define NUM_BOND_C 2
#define BN_EPS 1e-5f
#define MPAD_N 100096   // 782*128
#define MPAD_G 4096     // 32*128

// ---------------- scratch (device globals: no allocation allowed) ----------------
__device__ float g_h[(size_t)NN * DD];
__device__ float g_agg[(size_t)NN * DD];
__device__ float g_tmp[(size_t)NN * FDIM];
__device__ float g_stat[2 * FDIM];
__device__ float g_ab[2 * DD];
__device__ float g_ssum[(size_t)GG * FDIM];
__device__ float g_cnt[GG];
__device__ float g_gfeat[(size_t)GG * FDIM];
__device__ float g_hid[(size_t)GG * (FDIM / 2)];
// fp16 hi/lo fragment buffer for GEMM1 -> GEMM2 intermediate (K=512 operand)
__device__ uint4 g_a16b[(size_t)(MPAD_N / 16) * (FDIM / 16) * 64];
// B16 chunk = (8 cols x 16 k): 32 uint4 = [lane32][hi0,hi1,lo0,lo1]
// offsets (uint4): w1[l]@l*32768 | w2[l]@163840+l*32768 | feat@327680 | head@360448
__device__ uint4 g_w16[393216];

__device__ __forceinline__ float softplus_f(float x) {
    return fmaxf(x, 0.0f) + log1pf(expf(-fabsf(x)));
}

__device__ __forceinline__ void red_add_v4(float* p, float x, float y, float z, float w) {
    asm volatile("red.global.add.v4.f32 [%0], {%1,%2,%3,%4};"
                 :: "l"(p), "f"(x), "f"(y), "f"(z), "f"(w) : "memory");
}
__device__ __forceinline__ void red_add_f32(float* p, float v) {
    asm volatile("red.global.add.f32 [%0], %1;" :: "l"(p), "f"(v) : "memory");
}

// ---------------- fp16 split helpers ----------------
__device__ __forceinline__ void packhl(float x, float y, uint32_t& hi, uint32_t& lo) {
    __half2 h = __floats2half2_rn(x, y);             // low half = x
    float2 hf = __half22float2(h);
    __half2 l = __floats2half2_rn(x - hf.x, y - hf.y);
    hi = *reinterpret_cast<uint32_t*>(&h);
    lo = *reinterpret_cast<uint32_t*>(&l);
}

__device__ __forceinline__ void mma16(float* c, const uint32_t* a, uint32_t b0, uint32_t b1) {
    asm volatile(
        "mma.sync.aligned.m16n8k16.row.col.f32.f16.f16.f32 "
        "{%0,%1,%2,%3},{%4,%5,%6,%7},{%8,%9},{%0,%1,%2,%3};"
        : "+f"(c[0]), "+f"(c[1]), "+f"(c[2]), "+f"(c[3])
        : "r"(a[0]), "r"(a[1]), "r"(a[2]), "r"(a[3]), "r"(b0), "r"(b1));
}

__device__ __forceinline__ void cpa16(void* dst, const void* src, int srcBytes) {
    uint32_t d = (uint32_t)__cvta_generic_to_shared(dst);
    asm volatile("cp.async.cg.shared.global [%0], [%1], 16, %2;"
                 :: "r"(d), "l"(src), "r"(srcBytes) : "memory");
}
__device__ __forceinline__ void cpa16f(void* dst, const void* src) {
    uint32_t d = (uint32_t)__cvta_generic_to_shared(dst);
    asm volatile("cp.async.cg.shared.global [%0], [%1], 16;" :: "r"(d), "l"(src) : "memory");
}
__device__ __forceinline__ void cp_commit() {
    asm volatile("cp.async.commit_group;" ::: "memory");
}
__device__ __forceinline__ void cp_wait0() {
    asm volatile("cp.async.wait_group 0;" ::: "memory");
}

// ---------------- B16 converter (one warp per (8-col, 16-k) chunk; W is [K,N]) ------
__global__ void conv_b16(const float* __restrict__ W, uint4* __restrict__ dst, int K, int N) {
    int Q = K >> 4;
    int wid = blockIdx.x * (blockDim.x >> 5) + (threadIdx.x >> 5);
    int nch = (N >> 3) * Q;
    if (wid >= nch) return;
    int bn = wid / Q, q = wid - bn * Q;
    int lane = threadIdx.x & 31, g = lane >> 2, t = lane & 3;
    int n = bn * 8 + g;
    int k0 = q * 16 + 2 * t, k1 = k0 + 8;
    uint4 v;
    uint32_t l0, l1;
    packhl(W[(size_t)k0 * N + n], W[(size_t)(k0 + 1) * N + n], v.x, l0);
    packhl(W[(size_t)k1 * N + n], W[(size_t)(k1 + 1) * N + n], v.y, l1);
    v.z = l0;
    v.w = l1;
    dst[(size_t)wid * 32 + lane] = v;
}

// ---------------- fp16x3 tensor-core GEMM ----------------
// A: fragment-format [Mpad,K] (A16) OR fp32 row-major (Afp) staged through the same
//    cp.async pipeline (raw fp32 in smem, SW128-swizzled; converted at LDS time).
// B16 fragment-format [Nc, K]. 128x128 CTA tile, BK=32, 2-stage, 8 warps (4x2).
// outputs: C fp32 (opt), O16 fragment-format (opt), BN stats (opt).
// smem: per stage 2048 uint4 = A 1024 (16KB; frag OR fp32) + B 1024 (16KB). 64KB total.
#define GEMM_SMEM_BYTES 65536

__global__ __launch_bounds__(256, 2)
void gemm_f16(const uint4* __restrict__ A16, const float* __restrict__ Afp,
              const uint4* __restrict__ B16, const float* __restrict__ bias,
              float* __restrict__ C, uint4* __restrict__ O16, int M, int Qa, int Nc,
              int act, float* __restrict__ stat, int Qout) {
    extern __shared__ uint4 sm4[];
    const int tid = threadIdx.x, lane = tid & 31, w = tid >> 5;
    const int g = lane >> 2, t = lane & 3;
    const int wm = (w >> 1) * 32, wn = (w & 1) * 64;
    const int brow = blockIdx.y * 128, bcol = blockIdx.x * 128;
    const bool a32 = (Afp != nullptr);
    const int K = Qa << 4;

    // ---- frag-A cp.async descriptors (a16 mode) ----
    const uint4* asrc[4];
    uint4* adst[4];
    const uint4* bsrc[4];
    uint4* bdst[4];
#pragma unroll
    for (int j = 0; j < 4; j++) {
        int u = tid + j * 256;
        {
            int chunk = u >> 6, wd = u & 63;
            int bm = chunk >> 1, ql = chunk & 1;
            asrc[j] = A16 + ((size_t)((brow >> 4) + bm) * Qa + ql) * 64 + wd;
            adst[j] = sm4 + (ql * 8 + bm) * 64 + wd;
        }
        {
            int chunk = u >> 5, wd = u & 31;
            int bn = chunk >> 1, ql = chunk & 1;
            bsrc[j] = B16 + ((size_t)((bcol >> 3) + bn) * Qa + ql) * 32 + wd;
            bdst[j] = sm4 + 1024 + (ql * 16 + bn) * 32 + wd;
        }
    }

    // ---- fp32-A cp.async descriptors (a32 mode) ----
    // stage layout: 128 rows x 32 floats (128B/row), 16B chunks SW128-swizzled:
    // chunk c of row r stored at uint4 index r*8 + (c ^ (r&7)).
    const int ac = tid & 7;            // chunk 0..7
    const int ar0 = tid >> 3;          // row 0..31 (+32j)
    const int acsw = ac ^ (ar0 & 7);   // (row&7) invariant across j (+32)
    const float* asrc32[4];
    uint4* adst32[4];
    int aokb[4];
    if (a32) {
#pragma unroll
        for (int j = 0; j < 4; j++) {
            int row = ar0 + 32 * j;
            int rowg = brow + row;
            aokb[j] = (rowg < M) ? 16 : 0;
            asrc32[j] = Afp + (size_t)((rowg < M) ? rowg : 0) * K + ac * 4;
            adst32[j] = sm4 + row * 8 + acsw;
        }
    }

    float acc[2][8][4];
#pragma unroll
    for (int mt = 0; mt < 2; mt++)
#pragma unroll
        for (int nt = 0; nt < 8; nt++)
#pragma unroll
            for (int q = 0; q < 4; q++) acc[mt][nt][q] = 0.0f;

    const int S = Qa >> 1;

    // prologue: stage 0
    if (a32) {
#pragma unroll
        for (int j = 0; j < 4; j++) cpa16(adst32[j], asrc32[j], aokb[j]);
    } else {
#pragma unroll
        for (int j = 0; j < 4; j++) cpa16f(adst[j], asrc[j]);
    }
#pragma unroll
    for (int j = 0; j < 4; j++) cpa16f(bdst[j], bsrc[j]);
    cp_commit();

    for (int s = 0; s < S; s++) {
        const int st = s & 1;
        cp_wait0();
        __syncthreads();
        if (s + 1 < S) {
            const int st2 = st ^ 1;
            if (a32) {
#pragma unroll
                for (int j = 0; j < 4; j++)
                    cpa16(adst32[j] + st2 * 2048, asrc32[j] + (size_t)(s + 1) * 32, aokb[j]);
            } else {
#pragma unroll
                for (int j = 0; j < 4; j++)
                    cpa16f(adst[j] + st2 * 2048, asrc[j] + (size_t)(s + 1) * 128);
            }
#pragma unroll
            for (int j = 0; j < 4; j++)
                cpa16f(bdst[j] + st2 * 2048, bsrc[j] + (size_t)(s + 1) * 64);
        }
        cp_commit();

#pragma unroll
        for (int ql = 0; ql < 2; ql++) {
            uint4 ah[2], al[2];
            if (a32) {
                const float* As = (const float*)(sm4 + st * 2048);
#pragma unroll
                for (int mt = 0; mt < 2; mt++) {
                    const int r = wm + mt * 16 + g;      // r&7 == g
                    const int rb = r * 32;
                    const int c1 = ((ql * 4) | (t >> 1)) ^ g;
                    const int c2 = c1 ^ 2;
                    const int hw = (t & 1) * 2;
                    float2 f0 = *(const float2*)(As + rb + c1 * 4 + hw);          // (r,   2t)
                    float2 f1 = *(const float2*)(As + rb + 256 + c1 * 4 + hw);    // (r+8, 2t)
                    float2 f2 = *(const float2*)(As + rb + c2 * 4 + hw);          // (r,   2t+8)
                    float2 f3 = *(const float2*)(As + rb + 256 + c2 * 4 + hw);    // (r+8, 2t+8)
                    packhl(f0.x, f0.y, ah[mt].x, al[mt].x);
                    packhl(f1.x, f1.y, ah[mt].y, al[mt].y);
                    packhl(f2.x, f2.y, ah[mt].z, al[mt].z);
                    packhl(f3.x, f3.y, ah[mt].w, al[mt].w);
                }
            } else {
#pragma unroll
                for (int mt = 0; mt < 2; mt++) {
                    const uint4* ap = sm4 + st * 2048 + (ql * 8 + (wm >> 4) + mt) * 64;
                    ah[mt] = ap[lane];
                    al[mt] = ap[32 + lane];
                }
            }
#pragma unroll
            for (int nt = 0; nt < 8; nt++) {
                uint4 bv = sm4[st * 2048 + 1024 + (ql * 16 + (wn >> 3) + nt) * 32 + lane];
#pragma unroll
                for (int mt = 0; mt < 2; mt++) {
                    mma16(acc[mt][nt], (const uint32_t*)&ah[mt], bv.x, bv.y);
                    mma16(acc[mt][nt], (const uint32_t*)&ah[mt], bv.z, bv.w);
                    mma16(acc[mt][nt], (const uint32_t*)&al[mt], bv.x, bv.y);
                }
            }
        }
    }

    // ---------------- epilogue ----------------
    const bool do_stats = (stat != nullptr);
    float csum[16], csq[16];
    if (do_stats) {
#pragma unroll
        for (int i = 0; i < 16; i++) { csum[i] = 0.f; csq[i] = 0.f; }
    }

#pragma unroll
    for (int mt = 0; mt < 2; mt++) {
        const int r0 = brow + wm + mt * 16 + g;
        const int r1 = r0 + 8;
#pragma unroll
        for (int j = 0; j < 4; j++) {
            float v[2][4];
#pragma unroll
            for (int e = 0; e < 2; e++) {
                const int nt = j * 2 + e;
                const int col = bcol + wn + nt * 8 + t * 2;
                const float b0 = bias[col];
                const float b1 = bias[col + 1];
                float x0 = acc[mt][nt][0] + b0;
                float x1 = acc[mt][nt][1] + b1;
                float x2 = acc[mt][nt][2] + b0;
                float x3 = acc[mt][nt][3] + b1;
                if (act) {
                    x0 = softplus_f(x0); x1 = softplus_f(x1);
                    x2 = softplus_f(x2); x3 = softplus_f(x3);
                }
                if (r0 >= M) { x0 = 0.f; x1 = 0.f; }
                if (r1 >= M) { x2 = 0.f; x3 = 0.f; }
                v[e][0] = x0; v[e][1] = x1; v[e][2] = x2; v[e][3] = x3;
                if (C) {
                    if (r0 < M) *(float2*)&C[(size_t)r0 * Nc + col] = make_float2(x0, x1);
                    if (r1 < M) *(float2*)&C[(size_t)r1 * Nc + col] = make_float2(x2, x3);
                }
                if (do_stats) {
                    csum[nt * 2] += x0 + x2;
                    csq[nt * 2] += x0 * x0 + x2 * x2;
                    csum[nt * 2 + 1] += x1 + x3;
                    csq[nt * 2 + 1] += x1 * x1 + x3 * x3;
                }
            }
            if (O16) {
                uint4 hi, lo;
                packhl(v[0][0], v[0][1], hi.x, lo.x);
                packhl(v[0][2], v[0][3], hi.y, lo.y);
                packhl(v[1][0], v[1][1], hi.z, lo.z);
                packhl(v[1][2], v[1][3], hi.w, lo.w);
                size_t chunk = (size_t)((brow + wm + mt * 16) >> 4) * Qout +
                               ((bcol + wn) >> 4) + j;
                O16[chunk * 64 + lane] = hi;
                O16[chunk * 64 + 32 + lane] = lo;
            }
        }
    }

    if (do_stats) {
#pragma unroll
        for (int i = 0; i < 16; i++) {
            float sv = csum[i], qv = csq[i];
            sv += __shfl_xor_sync(0xffffffffu, sv, 4);
            sv += __shfl_xor_sync(0xffffffffu, sv, 8);
            sv += __shfl_xor_sync(0xffffffffu, sv, 16);
            qv += __shfl_xor_sync(0xffffffffu, qv, 4);
            qv += __shfl_xor_sync(0xffffffffu, qv, 8);
            qv += __shfl_xor_sync(0xffffffffu, qv, 16);
            if (g == 0) {
                const int col = bcol + wn + (i >> 1) * 8 + t * 2 + (i & 1);
                red_add_f32(&stat[col], sv);
                red_add_f32(&stat[Nc + col], qv);
            }
        }
    }
}

// ---------------- non-GEMM kernels ----------------
__global__ void init_h_kernel(const int* __restrict__ atomics,
                              const float* __restrict__ pos,
                              const float* __restrict__ emb1,
                              const float* __restrict__ w2,
                              const float* __restrict__ b2,
                              float* __restrict__ h) {
    size_t idx = (size_t)blockIdx.x * blockDim.x + threadIdx.x;
    if (idx >= (size_t)NN * DD) return;
    int i = (int)(idx / DD);
    int d = (int)(idx & (DD - 1));
    float p0 = pos[i * 3 + 0], p1 = pos[i * 3 + 1], p2 = pos[i * 3 + 2];
    float v = emb1[(size_t)atomics[i] * DD + d];
    v += p0 * w2[d] + p1 * w2[DD + d] + p2 * w2[2 * DD + d] + b2[d];
    h[idx] = v;
}

__global__ void agg_init_kernel(const float* __restrict__ h,
                                const float* __restrict__ emb_self,
                                float* __restrict__ agg) {
    size_t idx = (size_t)blockIdx.x * blockDim.x + threadIdx.x;
    if (idx >= (size_t)NN * DD / 4) return;
    int d4 = (int)(idx & (DD / 4 - 1)) * 4;
    float4 hv = *((const float4*)h + idx);
    float4 ev = *(const float4*)(emb_self + d4);
    *((float4*)agg + idx) = make_float4(hv.x + ev.x, hv.y + ev.y, hv.z + ev.z, hv.w + ev.w);
}

__global__ void scatter_edges_kernel(const float* __restrict__ h,
                                     const int* __restrict__ edge_index,
                                     const int* __restrict__ edge_attr,
                                     const float* __restrict__ emb,
                                     float* __restrict__ agg) {
    int e = blockIdx.x * (blockDim.x >> 5) + (threadIdx.x >> 5);
    if (e >= EE) return;
    int lane = threadIdx.x & 31;
    int s = edge_index[e];
    int t = edge_index[EE + e];
    const float* hs = h + (size_t)s * DD;
    const float* eb = emb + (size_t)edge_attr[e] * DD;
    float* ag = agg + (size_t)t * DD;
#pragma unroll
    for (int half = 0; half < 2; half++) {
        int c = lane * 4 + half * 128;
        float4 hv = *(const float4*)(hs + c);
        float4 ev = *(const float4*)(eb + c);
        red_add_v4(ag + c, hv.x + ev.x, hv.y + ev.y, hv.z + ev.z, hv.w + ev.w);
    }
}

__global__ void zero_kernel(float* __restrict__ p, size_t n) {
    size_t idx = (size_t)blockIdx.x * blockDim.x + threadIdx.x;
    if (idx < n) p[idx] = 0.0f;
}

__global__ void bn_finalize_kernel(const float* __restrict__ stat,
                                   const float* __restrict__ gamma,
                                   const float* __restrict__ beta,
                                   float* __restrict__ ab) {
    int d = threadIdx.x;
    float mean = stat[d] * (1.0f / NN);
    float var = stat[DD + d] * (1.0f / NN) - mean * mean;
    float inv = rsqrtf(var + BN_EPS);
    float a = gamma[d] * inv;
    ab[d] = a;
    ab[DD + d] = beta[d] - mean * a;
}

__global__ void bn_apply_agg_kernel(float* __restrict__ h, const float* __restrict__ ab,
                                    const float* __restrict__ emb_next,
                                    float* __restrict__ agg, int act) {
    size_t idx = (size_t)blockIdx.x * blockDim.x + threadIdx.x;
    if (idx >= (size_t)NN * DD / 4) return;
    int d4 = (int)(idx & (DD / 4 - 1)) * 4;
    float4 v = *((float4*)h + idx);
    float4 a = *(const float4*)(ab + d4);
    float4 b = *(const float4*)(ab + DD + d4);
    v.x = v.x * a.x + b.x;
    v.y = v.y * a.y + b.y;
    v.z = v.z * a.z + b.z;
    v.w = v.w * a.w + b.w;
    if (act) {
        v.x = softplus_f(v.x);
        v.y = softplus_f(v.y);
        v.z = softplus_f(v.z);
        v.w = softplus_f(v.w);
    }
    *((float4*)h + idx) = v;
    if (agg) {
        float4 e = *(const float4*)(emb_next + d4);
        *((float4*)agg + idx) = make_float4(v.x + e.x, v.y + e.y, v.z + e.z, v.w + e.w);
    }
}

__global__ void pool_count_kernel(const int* __restrict__ batch, float* __restrict__ cnt) {
    int i = blockIdx.x * blockDim.x + threadIdx.x;
    if (i >= NN) return;
    atomicAdd(&cnt[batch[i]], 1.0f);
}

__global__ void pool_sum_kernel(const float* __restrict__ feat,
                                const int* __restrict__ batch,
                                float* __restrict__ ssum) {
    size_t idx = (size_t)blockIdx.x * blockDim.x + threadIdx.x;
    const int CH = FDIM / 4;
    const size_t nchunks = (NN + 7) / 8;
    if (idx >= nchunks * CH) return;
    int f4 = (int)(idx & (CH - 1)) * 4;
    int i0 = (int)(idx / CH) * 8;
    int cur = batch[i0];
    float4 acc = make_float4(0.f, 0.f, 0.f, 0.f);
#pragma unroll
    for (int r = 0; r < 8; r++) {
        int i = i0 + r;
        if (i >= NN) break;
        int b = batch[i];
        if (b != cur) {
            red_add_v4(&ssum[(size_t)cur * FDIM + f4], acc.x, acc.y, acc.z, acc.w);
            acc = make_float4(0.f, 0.f, 0.f, 0.f);
            cur = b;
        }
        float4 v = *(const float4*)(feat + (size_t)i * FDIM + f4);
        acc.x += v.x; acc.y += v.y; acc.z += v.z; acc.w += v.w;
    }
    red_add_v4(&ssum[(size_t)cur * FDIM + f4], acc.x, acc.y, acc.z, acc.w);
}

__global__ void gfeat_kernel(const float* __restrict__ ssum, const float* __restrict__ cnt,
                             float* __restrict__ gfeat) {
    size_t idx = (size_t)blockIdx.x * blockDim.x + threadIdx.x;
    if (idx >= (size_t)GG * FDIM) return;
    int g = (int)(idx / FDIM);
    gfeat[idx] = ssum[idx] / fmaxf(cnt[g], 1.0f);
}

__global__ void head_out_kernel(const float* __restrict__ hid, const float* __restrict__ w2,
                                const float* __restrict__ b2, float* __restrict__ out) {
    int g = blockIdx.x * (blockDim.x >> 5) + (threadIdx.x >> 5);
    if (g >= GG) return;
    int lane = threadIdx.x & 31;
    const float* hr = hid + (size_t)g * (FDIM / 2);
    float s = 0.f;
#pragma unroll
    for (int k = lane; k < FDIM / 2; k += 32) s += hr[k] * w2[k];
#pragma unroll
    for (int o = 16; o; o >>= 1) s += __shfl_down_sync(0xffffffffu, s, o);
    if (lane == 0) out[g] = s + b2[0];
}

// ---------------- host launch ----------------
static inline void launch_gemm(const uint4* A16, const float* Afp, const uint4* B16,
                               const float* bias, float* C, uint4* O16, int M, int Mpad,
                               int Qa, int Nc, int act, float* stat, int Qout) {
    dim3 grid(Nc / 128, Mpad / 128);
    gemm_f16<<<grid, 256, GEMM_SMEM_BYTES>>>(A16, Afp, B16, bias, C, O16, M, Qa, Nc, act,
                                             stat, Qout);
}

extern "C" void kernel_launch(void* const* d_in, const int* in_sizes, int n_in,
                              void* d_out, int out_size) {
    const int* atomics = (const int*)d_in[0];
    const float* pos = (const float*)d_in[1];
    const int* edge_index = (const int*)d_in[2];
    const int* edge_attr = (const int*)d_in[3];
    const int* batch = (const int*)d_in[4];
    const float* x_emb1 = (const float*)d_in[5];
    const float* x_emb2_w = (const float*)d_in[6];
    const float* x_emb2_b = (const float*)d_in[7];
    const float* edge_emb = (const float*)d_in[8];
    const float* mlp_w1 = (const float*)d_in[9];
    const float* mlp_b1 = (const float*)d_in[10];
    const float* mlp_w2 = (const float*)d_in[11];
    const float* mlp_b2 = (const float*)d_in[12];
    const float* bn_gamma = (const float*)d_in[13];
    const float* bn_beta = (const float*)d_in[14];
    const float* feat_w = (const float*)d_in[15];
    const float* feat_b = (const float*)d_in[16];
    const float* head_w1 = (const float*)d_in[17];
    const float* head_b1 = (const float*)d_in[18];
    const float* head_w2 = (const float*)d_in[19];
    const float* head_b2 = (const float*)d_in[20];
    float* out = (float*)d_out;

    float *h, *agg, *tmp, *stat, *ab, *ssum, *cnt, *gfeat, *hid;
    uint4 *a16b, *w16;
    cudaGetSymbolAddress((void**)&h, g_h);
    cudaGetSymbolAddress((void**)&agg, g_agg);
    cudaGetSymbolAddress((void**)&tmp, g_tmp);
    cudaGetSymbolAddress((void**)&stat, g_stat);
    cudaGetSymbolAddress((void**)&ab, g_ab);
    cudaGetSymbolAddress((void**)&ssum, g_ssum);
    cudaGetSymbolAddress((void**)&cnt, g_cnt);
    cudaGetSymbolAddress((void**)&gfeat, g_gfeat);
    cudaGetSymbolAddress((void**)&hid, g_hid);
    cudaGetSymbolAddress((void**)&a16b, g_a16b);
    cudaGetSymbolAddress((void**)&w16, g_w16);

    cudaFuncSetAttribute(gemm_f16, cudaFuncAttributeMaxDynamicSharedMemorySize,
                         GEMM_SMEM_BYTES);

    const size_t ND = (size_t)NN * DD;
    const size_t ND4 = ND / 4;
    const int EL = 256;

    // ---- B16 prep ----
    for (int l = 0; l < LL; l++) {
        conv_b16<<<128, 256>>>(mlp_w1 + (size_t)l * DD * 2 * DD, w16 + l * 32768, DD, 2 * DD);
        conv_b16<<<128, 256>>>(mlp_w2 + (size_t)l * 2 * DD * DD, w16 + 163840 + l * 32768,
                               2 * DD, DD);
    }
    conv_b16<<<128, 256>>>(feat_w, w16 + 327680, DD, FDIM);
    conv_b16<<<128, 256>>>(head_w1, w16 + 360448, FDIM, FDIM / 2);

    init_h_kernel<<<(unsigned)((ND + EL - 1) / EL), EL>>>(atomics, pos, x_emb1, x_emb2_w,
                                                          x_emb2_b, h);
    {
        const float* emb_self0 =
            edge_emb + (size_t)0 * NUM_BOND_C * DD + (size_t)(NUM_BOND_C - 1) * DD;
        agg_init_kernel<<<(unsigned)((ND4 + EL - 1) / EL), EL>>>(h, emb_self0, agg);
    }

    for (int l = 0; l < LL; l++) {
        const float* emb_l = edge_emb + (size_t)l * NUM_BOND_C * DD;

        scatter_edges_kernel<<<(EE + 7) / 8, 256>>>(h, edge_index, edge_attr, emb_l, agg);

        // tmp16 = softplus(agg @ W1 + b1)  [N,512] fragment out; fp32 A via cp.async
        launch_gemm(nullptr, agg, w16 + l * 32768, mlp_b1 + (size_t)l * 2 * DD, nullptr,
                    a16b, NN, MPAD_N, DD / 16, 2 * DD, 1, nullptr, FDIM / 16);

        zero_kernel<<<1, 512>>>(stat, 2 * DD);
        // h = tmp16 @ W2 + b2 (+BN stats)  [N,256] fp32; fragment A
        launch_gemm(a16b, nullptr, w16 + 163840 + l * 32768, mlp_b2 + (size_t)l * DD, h,
                    nullptr, NN, MPAD_N, FDIM / 16, DD, 0, stat, 1);

        bn_finalize_kernel<<<1, 256>>>(stat, bn_gamma + (size_t)l * DD,
                                       bn_beta + (size_t)l * DD, ab);

        if (l < LL - 1) {
            const float* emb_self_next =
                edge_emb + (size_t)(l + 1) * NUM_BOND_C * DD + (size_t)(NUM_BOND_C - 1) * DD;
            bn_apply_agg_kernel<<<(unsigned)((ND4 + EL - 1) / EL), EL>>>(h, ab, emb_self_next,
                                                                         agg, 1);
        } else {
            bn_apply_agg_kernel<<<(unsigned)((ND4 + EL - 1) / EL), EL>>>(h, ab, nullptr,
                                                                         nullptr, 0);
        }
    }

    // feat = h @ feat_w + feat_b -> tmp fp32 (fp32 A)
    launch_gemm(nullptr, h, w16 + 327680, feat_b, tmp, nullptr, NN, MPAD_N, DD / 16, FDIM,
                0, nullptr, 1);

    // global mean pool
    zero_kernel<<<(unsigned)(((size_t)GG * FDIM + EL - 1) / EL), EL>>>(ssum, (size_t)GG * FDIM);
    zero_kernel<<<(GG + EL - 1) / EL, EL>>>(cnt, GG);
    pool_count_kernel<<<(NN + EL - 1) / EL, EL>>>(batch, cnt);
    {
        size_t total = ((NN + 7) / 8) * (size_t)(FDIM / 4);
        pool_sum_kernel<<<(unsigned)((total + EL - 1) / EL), EL>>>(tmp, batch, ssum);
    }
    gfeat_kernel<<<(unsigned)(((size_t)GG * FDIM + EL - 1) / EL), EL>>>(ssum, cnt, gfeat);

    // head: hid = softplus(gfeat @ head_w1 + head_b1)  (fp32 A)
    launch_gemm(nullptr, gfeat, w16 + 360448, head_b1, hid, nullptr, GG, MPAD_G, FDIM / 16,
                FDIM / 2, 1, nullptr, 1);
    head_out_kernel<<<(GG + 7) / 8, 256>>>(hid, head_w2, head_b2, out);
}

// round 11
// speedup vs baseline: 1.0814x; 1.0195x over previous
#include <cuda_runtime.h>
#include <cuda_fp16.h>
#include <math.h>
#include <stdint.h>

#define NN 100000
#define EE 300000
#define DD 256
#define FDIM 512
#define LL 5
#define GG 4000
#define NUM_BOND_C 2
#define BN_EPS 1e-5f
#define MPAD_N 100096   // 782*128
#define MPAD_G 4096     // 32*128
#define NB_SCAN 391     // ceil(NN/256)

// ---------------- scratch (device globals: no allocation allowed) ----------------
__device__ float g_h[(size_t)NN * DD];
__device__ float g_agg[(size_t)NN * DD];
__device__ float g_tmp[(size_t)NN * FDIM];
__device__ float g_stat[2 * FDIM];
__device__ float g_ab[2 * DD];
__device__ float g_ssum[(size_t)GG * FDIM];
__device__ float g_cnt[GG];
__device__ float g_gfeat[(size_t)GG * FDIM];
__device__ float g_hid[(size_t)GG * (FDIM / 2)];
// fp16 hi/lo fragment buffer for GEMM1 -> GEMM2 intermediate (K=512 operand)
__device__ uint4 g_a16b[(size_t)(MPAD_N / 16) * (FDIM / 16) * 64];
// B16 weights
__device__ uint4 g_w16[393216];
// CSR (by destination)
__device__ int g_deg[NN];
__device__ int g_fill[NN];
__device__ int g_rs[NN + 1];
__device__ int g_bsum[512];
__device__ int g_srcs[EE];
__device__ int g_attrs[EE];

__device__ __forceinline__ float softplus_f(float x) {
    return fmaxf(x, 0.0f) + log1pf(expf(-fabsf(x)));
}

__device__ __forceinline__ void red_add_f32(float* p, float v) {
    asm volatile("red.global.add.f32 [%0], %1;" :: "l"(p), "f"(v) : "memory");
}
__device__ __forceinline__ void red_add_v4(float* p, float x, float y, float z, float w) {
    asm volatile("red.global.add.v4.f32 [%0], {%1,%2,%3,%4};"
                 :: "l"(p), "f"(x), "f"(y), "f"(z), "f"(w) : "memory");
}

// ---------------- fp16 split helpers ----------------
__device__ __forceinline__ void packhl(float x, float y, uint32_t& hi, uint32_t& lo) {
    __half2 h = __floats2half2_rn(x, y);
    float2 hf = __half22float2(h);
    __half2 l = __floats2half2_rn(x - hf.x, y - hf.y);
    hi = *reinterpret_cast<uint32_t*>(&h);
    lo = *reinterpret_cast<uint32_t*>(&l);
}

__device__ __forceinline__ void mma16(float* c, const uint32_t* a, uint32_t b0, uint32_t b1) {
    asm volatile(
        "mma.sync.aligned.m16n8k16.row.col.f32.f16.f16.f32 "
        "{%0,%1,%2,%3},{%4,%5,%6,%7},{%8,%9},{%0,%1,%2,%3};"
        : "+f"(c[0]), "+f"(c[1]), "+f"(c[2]), "+f"(c[3])
        : "r"(a[0]), "r"(a[1]), "r"(a[2]), "r"(a[3]), "r"(b0), "r"(b1));
}

__device__ __forceinline__ void cpa16(void* dst, const void* src, int srcBytes) {
    uint32_t d = (uint32_t)__cvta_generic_to_shared(dst);
    asm volatile("cp.async.cg.shared.global [%0], [%1], 16, %2;"
                 :: "r"(d), "l"(src), "r"(srcBytes) : "memory");
}
__device__ __forceinline__ void cpa16f(void* dst, const void* src) {
    uint32_t d = (uint32_t)__cvta_generic_to_shared(dst);
    asm volatile("cp.async.cg.shared.global [%0], [%1], 16;" :: "r"(d), "l"(src) : "memory");
}
__device__ __forceinline__ void cp_commit() {
    asm volatile("cp.async.commit_group;" ::: "memory");
}
__device__ __forceinline__ void cp_wait0() {
    asm volatile("cp.async.wait_group 0;" ::: "memory");
}

// ---------------- CSR build ----------------
__global__ void csr_zero(int* deg, int* fill) {
    int i = blockIdx.x * blockDim.x + threadIdx.x;
    if (i < NN) { deg[i] = 0; fill[i] = 0; }
}
__global__ void csr_count(const int* __restrict__ edge_index, int* __restrict__ deg) {
    int e = blockIdx.x * blockDim.x + threadIdx.x;
    if (e < EE) atomicAdd(&deg[edge_index[EE + e]], 1);
}
__global__ void csr_scan1(const int* __restrict__ deg, int* __restrict__ rs,
                          int* __restrict__ bsum) {
    __shared__ int sm[256];
    int tid = threadIdx.x;
    int i = blockIdx.x * 256 + tid;
    int v = (i < NN) ? deg[i] : 0;
    sm[tid] = v;
    __syncthreads();
#pragma unroll
    for (int o = 1; o < 256; o <<= 1) {
        int t = (tid >= o) ? sm[tid - o] : 0;
        __syncthreads();
        if (tid >= o) sm[tid] += t;
        __syncthreads();
    }
    if (i < NN) rs[i] = sm[tid] - v;
    if (tid == 255) bsum[blockIdx.x] = sm[255];
}
__global__ void csr_scan2(int* __restrict__ bsum) {
    __shared__ int sm[512];
    int tid = threadIdx.x;
    int v = (tid < NB_SCAN) ? bsum[tid] : 0;
    sm[tid] = v;
    __syncthreads();
#pragma unroll
    for (int o = 1; o < 512; o <<= 1) {
        int t = (tid >= o) ? sm[tid - o] : 0;
        __syncthreads();
        if (tid >= o) sm[tid] += t;
        __syncthreads();
    }
    if (tid < NB_SCAN) bsum[tid] = sm[tid] - v;  // exclusive
}
__global__ void csr_scan3(int* __restrict__ rs, const int* __restrict__ bsum) {
    int i = blockIdx.x * 256 + threadIdx.x;
    if (i < NN) rs[i] += bsum[blockIdx.x];
    if (i == 0) rs[NN] = EE;
}
__global__ void csr_place(const int* __restrict__ edge_index,
                          const int* __restrict__ edge_attr,
                          const int* __restrict__ rs, int* __restrict__ fill,
                          int* __restrict__ srcs, int* __restrict__ attrs) {
    int e = blockIdx.x * blockDim.x + threadIdx.x;
    if (e >= EE) return;
    int d = edge_index[EE + e];
    int p = rs[d] + atomicAdd(&fill[d], 1);
    srcs[p] = edge_index[e];
    attrs[p] = edge_attr[e];
}

// ---------------- gather: agg[i] = h[i]+emb_self + sum_in (h[src]+emb[attr]) ---------
__global__ void gather_edges_kernel(const float* __restrict__ h,
                                    const int* __restrict__ srcs,
                                    const int* __restrict__ attrs,
                                    const int* __restrict__ rs,
                                    const float* __restrict__ emb,   // layer slice [2][256]
                                    float* __restrict__ agg) {
    int node = blockIdx.x * (blockDim.x >> 5) + (threadIdx.x >> 5);
    if (node >= NN) return;
    int lane = threadIdx.x & 31;
    int c0 = lane * 4, c1 = c0 + 128;
    const float* hn = h + (size_t)node * DD;
    const float* es = emb + (size_t)(NUM_BOND_C - 1) * DD;
    float4 v0 = *(const float4*)(hn + c0);
    float4 v1 = *(const float4*)(hn + c1);
    float4 e0 = *(const float4*)(es + c0);
    float4 e1 = *(const float4*)(es + c1);
    float4 a0 = make_float4(v0.x + e0.x, v0.y + e0.y, v0.z + e0.z, v0.w + e0.w);
    float4 a1 = make_float4(v1.x + e1.x, v1.y + e1.y, v1.z + e1.z, v1.w + e1.w);
    int p0 = rs[node], p1 = rs[node + 1];
    for (int p = p0; p < p1; p++) {
        int s = srcs[p], a = attrs[p];
        const float* hs = h + (size_t)s * DD;
        const float* eb = emb + (size_t)a * DD;
        float4 h0 = *(const float4*)(hs + c0);
        float4 h1 = *(const float4*)(hs + c1);
        float4 b0 = *(const float4*)(eb + c0);
        float4 b1 = *(const float4*)(eb + c1);
        a0.x += h0.x + b0.x; a0.y += h0.y + b0.y; a0.z += h0.z + b0.z; a0.w += h0.w + b0.w;
        a1.x += h1.x + b1.x; a1.y += h1.y + b1.y; a1.z += h1.z + b1.z; a1.w += h1.w + b1.w;
    }
    float* ag = agg + (size_t)node * DD;
    *(float4*)(ag + c0) = a0;
    *(float4*)(ag + c1) = a1;
}

// ---------------- B16 converter ----------------
__global__ void conv_b16(const float* __restrict__ W, uint4* __restrict__ dst, int K, int N) {
    int Q = K >> 4;
    int wid = blockIdx.x * (blockDim.x >> 5) + (threadIdx.x >> 5);
    int nch = (N >> 3) * Q;
    if (wid >= nch) return;
    int bn = wid / Q, q = wid - bn * Q;
    int lane = threadIdx.x & 31, g = lane >> 2, t = lane & 3;
    int n = bn * 8 + g;
    int k0 = q * 16 + 2 * t, k1 = k0 + 8;
    uint4 v;
    uint32_t l0, l1;
    packhl(W[(size_t)k0 * N + n], W[(size_t)(k0 + 1) * N + n], v.x, l0);
    packhl(W[(size_t)k1 * N + n], W[(size_t)(k1 + 1) * N + n], v.y, l1);
    v.z = l0;
    v.w = l1;
    dst[(size_t)wid * 32 + lane] = v;
}

// ---------------- fp16x3 tensor-core GEMM (R10 structure) ----------------
#define GEMM_SMEM_BYTES 65536

__global__ __launch_bounds__(256, 2)
void gemm_f16(const uint4* __restrict__ A16, const float* __restrict__ Afp,
              const uint4* __restrict__ B16, const float* __restrict__ bias,
              float* __restrict__ C, uint4* __restrict__ O16, int M, int Qa, int Nc,
              int act, float* __restrict__ stat, int Qout) {
    extern __shared__ uint4 sm4[];
    const int tid = threadIdx.x, lane = tid & 31, w = tid >> 5;
    const int g = lane >> 2, t = lane & 3;
    const int wm = (w >> 1) * 32, wn = (w & 1) * 64;
    const int brow = blockIdx.y * 128, bcol = blockIdx.x * 128;
    const bool a32 = (Afp != nullptr);
    const int K = Qa << 4;

    const uint4* asrc[4];
    uint4* adst[4];
    const uint4* bsrc[4];
    uint4* bdst[4];
#pragma unroll
    for (int j = 0; j < 4; j++) {
        int u = tid + j * 256;
        {
            int chunk = u >> 6, wd = u & 63;
            int bm = chunk >> 1, ql = chunk & 1;
            asrc[j] = A16 + ((size_t)((brow >> 4) + bm) * Qa + ql) * 64 + wd;
            adst[j] = sm4 + (ql * 8 + bm) * 64 + wd;
        }
        {
            int chunk = u >> 5, wd = u & 31;
            int bn = chunk >> 1, ql = chunk & 1;
            bsrc[j] = B16 + ((size_t)((bcol >> 3) + bn) * Qa + ql) * 32 + wd;
            bdst[j] = sm4 + 1024 + (ql * 16 + bn) * 32 + wd;
        }
    }

    const int ac = tid & 7;
    const int ar0 = tid >> 3;
    const int acsw = ac ^ (ar0 & 7);
    const float* asrc32[4];
    uint4* adst32[4];
    int aokb[4];
    if (a32) {
#pragma unroll
        for (int j = 0; j < 4; j++) {
            int row = ar0 + 32 * j;
            int rowg = brow + row;
            aokb[j] = (rowg < M) ? 16 : 0;
            asrc32[j] = Afp + (size_t)((rowg < M) ? rowg : 0) * K + ac * 4;
            adst32[j] = sm4 + row * 8 + acsw;
        }
    }

    float acc[2][8][4];
#pragma unroll
    for (int mt = 0; mt < 2; mt++)
#pragma unroll
        for (int nt = 0; nt < 8; nt++)
#pragma unroll
            for (int q = 0; q < 4; q++) acc[mt][nt][q] = 0.0f;

    const int S = Qa >> 1;

    if (a32) {
#pragma unroll
        for (int j = 0; j < 4; j++) cpa16(adst32[j], asrc32[j], aokb[j]);
    } else {
#pragma unroll
        for (int j = 0; j < 4; j++) cpa16f(adst[j], asrc[j]);
    }
#pragma unroll
    for (int j = 0; j < 4; j++) cpa16f(bdst[j], bsrc[j]);
    cp_commit();

    for (int s = 0; s < S; s++) {
        const int st = s & 1;
        cp_wait0();
        __syncthreads();
        if (s + 1 < S) {
            const int st2 = st ^ 1;
            if (a32) {
#pragma unroll
                for (int j = 0; j < 4; j++)
                    cpa16(adst32[j] + st2 * 2048, asrc32[j] + (size_t)(s + 1) * 32, aokb[j]);
            } else {
#pragma unroll
                for (int j = 0; j < 4; j++)
                    cpa16f(adst[j] + st2 * 2048, asrc[j] + (size_t)(s + 1) * 128);
            }
#pragma unroll
            for (int j = 0; j < 4; j++)
                cpa16f(bdst[j] + st2 * 2048, bsrc[j] + (size_t)(s + 1) * 64);
        }
        cp_commit();

#pragma unroll
        for (int ql = 0; ql < 2; ql++) {
            uint4 ah[2], al[2];
            if (a32) {
                const float* As = (const float*)(sm4 + st * 2048);
#pragma unroll
                for (int mt = 0; mt < 2; mt++) {
                    const int r = wm + mt * 16 + g;
                    const int rb = r * 32;
                    const int c1 = ((ql * 4) | (t >> 1)) ^ g;
                    const int c2 = c1 ^ 2;
                    const int hw = (t & 1) * 2;
                    float2 f0 = *(const float2*)(As + rb + c1 * 4 + hw);
                    float2 f1 = *(const float2*)(As + rb + 256 + c1 * 4 + hw);
                    float2 f2 = *(const float2*)(As + rb + c2 * 4 + hw);
                    float2 f3 = *(const float2*)(As + rb + 256 + c2 * 4 + hw);
                    packhl(f0.x, f0.y, ah[mt].x, al[mt].x);
                    packhl(f1.x, f1.y, ah[mt].y, al[mt].y);
                    packhl(f2.x, f2.y, ah[mt].z, al[mt].z);
                    packhl(f3.x, f3.y, ah[mt].w, al[mt].w);
                }
            } else {
#pragma unroll
                for (int mt = 0; mt < 2; mt++) {
                    const uint4* ap = sm4 + st * 2048 + (ql * 8 + (wm >> 4) + mt) * 64;
                    ah[mt] = ap[lane];
                    al[mt] = ap[32 + lane];
                }
            }
#pragma unroll
            for (int nt = 0; nt < 8; nt++) {
                uint4 bv = sm4[st * 2048 + 1024 + (ql * 16 + (wn >> 3) + nt) * 32 + lane];
#pragma unroll
                for (int mt = 0; mt < 2; mt++) {
                    mma16(acc[mt][nt], (const uint32_t*)&ah[mt], bv.x, bv.y);
                    mma16(acc[mt][nt], (const uint32_t*)&ah[mt], bv.z, bv.w);
                    mma16(acc[mt][nt], (const uint32_t*)&al[mt], bv.x, bv.y);
                }
            }
        }
    }

    const bool do_stats = (stat != nullptr);
    float csum[16], csq[16];
    if (do_stats) {
#pragma unroll
        for (int i = 0; i < 16; i++) { csum[i] = 0.f; csq[i] = 0.f; }
    }

#pragma unroll
    for (int mt = 0; mt < 2; mt++) {
        const int r0 = brow + wm + mt * 16 + g;
        const int r1 = r0 + 8;
#pragma unroll
        for (int j = 0; j < 4; j++) {
            float v[2][4];
#pragma unroll
            for (int e = 0; e < 2; e++) {
                const int nt = j * 2 + e;
                const int col = bcol + wn + nt * 8 + t * 2;
                const float b0 = bias[col];
                const float b1 = bias[col + 1];
                float x0 = acc[mt][nt][0] + b0;
                float x1 = acc[mt][nt][1] + b1;
                float x2 = acc[mt][nt][2] + b0;
                float x3 = acc[mt][nt][3] + b1;
                if (act) {
                    x0 = softplus_f(x0); x1 = softplus_f(x1);
                    x2 = softplus_f(x2); x3 = softplus_f(x3);
                }
                if (r0 >= M) { x0 = 0.f; x1 = 0.f; }
                if (r1 >= M) { x2 = 0.f; x3 = 0.f; }
                v[e][0] = x0; v[e][1] = x1; v[e][2] = x2; v[e][3] = x3;
                if (C) {
                    if (r0 < M) *(float2*)&C[(size_t)r0 * Nc + col] = make_float2(x0, x1);
                    if (r1 < M) *(float2*)&C[(size_t)r1 * Nc + col] = make_float2(x2, x3);
                }
                if (do_stats) {
                    csum[nt * 2] += x0 + x2;
                    csq[nt * 2] += x0 * x0 + x2 * x2;
                    csum[nt * 2 + 1] += x1 + x3;
                    csq[nt * 2 + 1] += x1 * x1 + x3 * x3;
                }
            }
            if (O16) {
                uint4 hi, lo;
                packhl(v[0][0], v[0][1], hi.x, lo.x);
                packhl(v[0][2], v[0][3], hi.y, lo.y);
                packhl(v[1][0], v[1][1], hi.z, lo.z);
                packhl(v[1][2], v[1][3], hi.w, lo.w);
                size_t chunk = (size_t)((brow + wm + mt * 16) >> 4) * Qout +
                               ((bcol + wn) >> 4) + j;
                O16[chunk * 64 + lane] = hi;
                O16[chunk * 64 + 32 + lane] = lo;
            }
        }
    }

    if (do_stats) {
#pragma unroll
        for (int i = 0; i < 16; i++) {
            float sv = csum[i], qv = csq[i];
            sv += __shfl_xor_sync(0xffffffffu, sv, 4);
            sv += __shfl_xor_sync(0xffffffffu, sv, 8);
            sv += __shfl_xor_sync(0xffffffffu, sv, 16);
            qv += __shfl_xor_sync(0xffffffffu, qv, 4);
            qv += __shfl_xor_sync(0xffffffffu, qv, 8);
            qv += __shfl_xor_sync(0xffffffffu, qv, 16);
            if (g == 0) {
                const int col = bcol + wn + (i >> 1) * 8 + t * 2 + (i & 1);
                red_add_f32(&stat[col], sv);
                red_add_f32(&stat[Nc + col], qv);
            }
        }
    }
}

// ---------------- non-GEMM kernels ----------------
__global__ void init_h_kernel(const int* __restrict__ atomics,
                              const float* __restrict__ pos,
                              const float* __restrict__ emb1,
                              const float* __restrict__ w2,
                              const float* __restrict__ b2,
                              float* __restrict__ h) {
    size_t idx = (size_t)blockIdx.x * blockDim.x + threadIdx.x;
    if (idx >= (size_t)NN * DD) return;
    int i = (int)(idx / DD);
    int d = (int)(idx & (DD - 1));
    float p0 = pos[i * 3 + 0], p1 = pos[i * 3 + 1], p2 = pos[i * 3 + 2];
    float v = emb1[(size_t)atomics[i] * DD + d];
    v += p0 * w2[d] + p1 * w2[DD + d] + p2 * w2[2 * DD + d] + b2[d];
    h[idx] = v;
}

__global__ void zero_kernel(float* __restrict__ p, size_t n) {
    size_t idx = (size_t)blockIdx.x * blockDim.x + threadIdx.x;
    if (idx < n) p[idx] = 0.0f;
}

__global__ void bn_finalize_kernel(const float* __restrict__ stat,
                                   const float* __restrict__ gamma,
                                   const float* __restrict__ beta,
                                   float* __restrict__ ab) {
    int d = threadIdx.x;
    float mean = stat[d] * (1.0f / NN);
    float var = stat[DD + d] * (1.0f / NN) - mean * mean;
    float inv = rsqrtf(var + BN_EPS);
    float a = gamma[d] * inv;
    ab[d] = a;
    ab[DD + d] = beta[d] - mean * a;
}

__global__ void bn_apply_kernel(float* __restrict__ h, const float* __restrict__ ab,
                                int act) {
    size_t idx = (size_t)blockIdx.x * blockDim.x + threadIdx.x;
    if (idx >= (size_t)NN * DD / 4) return;
    int d4 = (int)(idx & (DD / 4 - 1)) * 4;
    float4 v = *((float4*)h + idx);
    float4 a = *(const float4*)(ab + d4);
    float4 b = *(const float4*)(ab + DD + d4);
    v.x = v.x * a.x + b.x;
    v.y = v.y * a.y + b.y;
    v.z = v.z * a.z + b.z;
    v.w = v.w * a.w + b.w;
    if (act) {
        v.x = softplus_f(v.x);
        v.y = softplus_f(v.y);
        v.z = softplus_f(v.z);
        v.w = softplus_f(v.w);
    }
    *((float4*)h + idx) = v;
}

__global__ void pool_count_kernel(const int* __restrict__ batch, float* __restrict__ cnt) {
    int i = blockIdx.x * blockDim.x + threadIdx.x;
    if (i >= NN) return;
    atomicAdd(&cnt[batch[i]], 1.0f);
}

__global__ void pool_sum_kernel(const float* __restrict__ feat,
                                const int* __restrict__ batch,
                                float* __restrict__ ssum) {
    size_t idx = (size_t)blockIdx.x * blockDim.x + threadIdx.x;
    const int CH = FDIM / 4;
    const size_t nchunks = (NN + 7) / 8;
    if (idx >= nchunks * CH) return;
    int f4 = (int)(idx & (CH - 1)) * 4;
    int i0 = (int)(idx / CH) * 8;
    int cur = batch[i0];
    float4 acc = make_float4(0.f, 0.f, 0.f, 0.f);
#pragma unroll
    for (int r = 0; r < 8; r++) {
        int i = i0 + r;
        if (i >= NN) break;
        int b = batch[i];
        if (b != cur) {
            red_add_v4(&ssum[(size_t)cur * FDIM + f4], acc.x, acc.y, acc.z, acc.w);
            acc = make_float4(0.f, 0.f, 0.f, 0.f);
            cur = b;
        }
        float4 v = *(const float4*)(feat + (size_t)i * FDIM + f4);
        acc.x += v.x; acc.y += v.y; acc.z += v.z; acc.w += v.w;
    }
    red_add_v4(&ssum[(size_t)cur * FDIM + f4], acc.x, acc.y, acc.z, acc.w);
}

__global__ void gfeat_kernel(const float* __restrict__ ssum, const float* __restrict__ cnt,
                             float* __restrict__ gfeat) {
    size_t idx = (size_t)blockIdx.x * blockDim.x + threadIdx.x;
    if (idx >= (size_t)GG * FDIM) return;
    int g = (int)(idx / FDIM);
    gfeat[idx] = ssum[idx] / fmaxf(cnt[g], 1.0f);
}

__global__ void head_out_kernel(const float* __restrict__ hid, const float* __restrict__ w2,
                                const float* __restrict__ b2, float* __restrict__ out) {
    int g = blockIdx.x * (blockDim.x >> 5) + (threadIdx.x >> 5);
    if (g >= GG) return;
    int lane = threadIdx.x & 31;
    const float* hr = hid + (size_t)g * (FDIM / 2);
    float s = 0.f;
#pragma unroll
    for (int k = lane; k < FDIM / 2; k += 32) s += hr[k] * w2[k];
#pragma unroll
    for (int o = 16; o; o >>= 1) s += __shfl_down_sync(0xffffffffu, s, o);
    if (lane == 0) out[g] = s + b2[0];
}

// ---------------- host launch ----------------
static inline void launch_gemm(const uint4* A16, const float* Afp, const uint4* B16,
                               const float* bias, float* C, uint4* O16, int M, int Mpad,
                               int Qa, int Nc, int act, float* stat, int Qout) {
    dim3 grid(Nc / 128, Mpad / 128);
    gemm_f16<<<grid, 256, GEMM_SMEM_BYTES>>>(A16, Afp, B16, bias, C, O16, M, Qa, Nc, act,
                                             stat, Qout);
}

extern "C" void kernel_launch(void* const* d_in, const int* in_sizes, int n_in,
                              void* d_out, int out_size) {
    const int* atomics = (const int*)d_in[0];
    const float* pos = (const float*)d_in[1];
    const int* edge_index = (const int*)d_in[2];
    const int* edge_attr = (const int*)d_in[3];
    const int* batch = (const int*)d_in[4];
    const float* x_emb1 = (const float*)d_in[5];
    const float* x_emb2_w = (const float*)d_in[6];
    const float* x_emb2_b = (const float*)d_in[7];
    const float* edge_emb = (const float*)d_in[8];
    const float* mlp_w1 = (const float*)d_in[9];
    const float* mlp_b1 = (const float*)d_in[10];
    const float* mlp_w2 = (const float*)d_in[11];
    const float* mlp_b2 = (const float*)d_in[12];
    const float* bn_gamma = (const float*)d_in[13];
    const float* bn_beta = (const float*)d_in[14];
    const float* feat_w = (const float*)d_in[15];
    const float* feat_b = (const float*)d_in[16];
    const float* head_w1 = (const float*)d_in[17];
    const float* head_b1 = (const float*)d_in[18];
    const float* head_w2 = (const float*)d_in[19];
    const float* head_b2 = (const float*)d_in[20];
    float* out = (float*)d_out;

    float *h, *agg, *tmp, *stat, *ab, *ssum, *cnt, *gfeat, *hid;
    uint4 *a16b, *w16;
    int *deg, *fill, *rs, *bsum, *srcs, *attrs;
    cudaGetSymbolAddress((void**)&h, g_h);
    cudaGetSymbolAddress((void**)&agg, g_agg);
    cudaGetSymbolAddress((void**)&tmp, g_tmp);
    cudaGetSymbolAddress((void**)&stat, g_stat);
    cudaGetSymbolAddress((void**)&ab, g_ab);
    cudaGetSymbolAddress((void**)&ssum, g_ssum);
    cudaGetSymbolAddress((void**)&cnt, g_cnt);
    cudaGetSymbolAddress((void**)&gfeat, g_gfeat);
    cudaGetSymbolAddress((void**)&hid, g_hid);
    cudaGetSymbolAddress((void**)&a16b, g_a16b);
    cudaGetSymbolAddress((void**)&w16, g_w16);
    cudaGetSymbolAddress((void**)&deg, g_deg);
    cudaGetSymbolAddress((void**)&fill, g_fill);
    cudaGetSymbolAddress((void**)&rs, g_rs);
    cudaGetSymbolAddress((void**)&bsum, g_bsum);
    cudaGetSymbolAddress((void**)&srcs, g_srcs);
    cudaGetSymbolAddress((void**)&attrs, g_attrs);

    cudaFuncSetAttribute(gemm_f16, cudaFuncAttributeMaxDynamicSharedMemorySize,
                         GEMM_SMEM_BYTES);

    const size_t ND = (size_t)NN * DD;
    const size_t ND4 = ND / 4;
    const int EL = 256;

    // ---- CSR build (per call; deterministic enough: tolerance-validated fp sums) ----
    csr_zero<<<(NN + EL - 1) / EL, EL>>>(deg, fill);
    csr_count<<<(EE + EL - 1) / EL, EL>>>(edge_index, deg);
    csr_scan1<<<NB_SCAN, 256>>>(deg, rs, bsum);
    csr_scan2<<<1, 512>>>(bsum);
    csr_scan3<<<NB_SCAN, 256>>>(rs, bsum);
    csr_place<<<(EE + EL - 1) / EL, EL>>>(edge_index, edge_attr, rs, fill, srcs, attrs);

    // ---- B16 prep ----
    for (int l = 0; l < LL; l++) {
        conv_b16<<<128, 256>>>(mlp_w1 + (size_t)l * DD * 2 * DD, w16 + l * 32768, DD, 2 * DD);
        conv_b16<<<128, 256>>>(mlp_w2 + (size_t)l * 2 * DD * DD, w16 + 163840 + l * 32768,
                               2 * DD, DD);
    }
    conv_b16<<<128, 256>>>(feat_w, w16 + 327680, DD, FDIM);
    conv_b16<<<128, 256>>>(head_w1, w16 + 360448, FDIM, FDIM / 2);

    init_h_kernel<<<(unsigned)((ND + EL - 1) / EL), EL>>>(atomics, pos, x_emb1, x_emb2_w,
                                                          x_emb2_b, h);

    for (int l = 0; l < LL; l++) {
        const float* emb_l = edge_emb + (size_t)l * NUM_BOND_C * DD;

        // agg = self + incoming (CSR gather, no atomics)
        gather_edges_kernel<<<(NN + 7) / 8, 256>>>(h, srcs, attrs, rs, emb_l, agg);

        // tmp16 = softplus(agg @ W1 + b1)  [N,512] fragment out (fp32 A via cp.async)
        launch_gemm(nullptr, agg, w16 + l * 32768, mlp_b1 + (size_t)l * 2 * DD, nullptr,
                    a16b, NN, MPAD_N, DD / 16, 2 * DD, 1, nullptr, FDIM / 16);

        zero_kernel<<<1, 512>>>(stat, 2 * DD);
        // h = tmp16 @ W2 + b2 (+BN stats)  [N,256] fp32 (fragment A)
        launch_gemm(a16b, nullptr, w16 + 163840 + l * 32768, mlp_b2 + (size_t)l * DD, h,
                    nullptr, NN, MPAD_N, FDIM / 16, DD, 0, stat, 1);

        bn_finalize_kernel<<<1, 256>>>(stat, bn_gamma + (size_t)l * DD,
                                       bn_beta + (size_t)l * DD, ab);
        bn_apply_kernel<<<(unsigned)((ND4 + EL - 1) / EL), EL>>>(h, ab, (l < LL - 1) ? 1 : 0);
    }

    // feat = h @ feat_w + feat_b -> tmp fp32 (fp32 A)
    launch_gemm(nullptr, h, w16 + 327680, feat_b, tmp, nullptr, NN, MPAD_N, DD / 16, FDIM,
                0, nullptr, 1);

    // global mean pool
    zero_kernel<<<(unsigned)(((size_t)GG * FDIM + EL - 1) / EL), EL>>>(ssum, (size_t)GG * FDIM);
    zero_kernel<<<(GG + EL - 1) / EL, EL>>>(cnt, GG);
    pool_count_kernel<<<(NN + EL - 1) / EL, EL>>>(batch, cnt);
    {
        size_t total = ((NN + 7) / 8) * (size_t)(FDIM / 4);
        pool_sum_kernel<<<(unsigned)((total + EL - 1) / EL), EL>>>(tmp, batch, ssum);
    }
    gfeat_kernel<<<(unsigned)(((size_t)GG * FDIM + EL - 1) / EL), EL>>>(ssum, cnt, gfeat);

    // head: hid = softplus(gfeat @ head_w1 + head_b1)  (fp32 A)
    launch_gemm(nullptr, gfeat, w16 + 360448, head_b1, hid, nullptr, GG, MPAD_G, FDIM / 16,
                FDIM / 2, 1, nullptr, 1);
    head_out_kernel<<<(GG + 7) / 8, 256>>>(hid, head_w2, head_b2, out);
}

// round 12
// speedup vs baseline: 1.1771x; 1.0885x over previous
#include <cuda_runtime.h>
#include <cuda_fp16.h>
#include <math.h>
#include <stdint.h>

#define NN 100000
#define EE 300000
#define DD 256
#define FDIM 512
#define LL 5
#define GG 4000
#define NUM_BOND_C 2
#define BN_EPS 1e-5f
#define MPAD_N 100096   // 782*128
#define MPAD_G 4096     // 32*128
#define NB_SCAN 391     // ceil(NN/256)

// ---------------- scratch (device globals: no allocation allowed) ----------------
__device__ float g_h[(size_t)NN * DD];
__device__ float g_agg[(size_t)NN * DD];
__device__ float g_stat[2 * FDIM];
__device__ float g_ab[2 * DD];
__device__ float g_ssum[(size_t)GG * FDIM];
__device__ float g_cnt[GG];
__device__ float g_pm[(size_t)GG * DD];      // pooled (BN-affine applied) means
__device__ float g_gfeat[(size_t)GG * FDIM];
__device__ float g_hid[(size_t)GG * (FDIM / 2)];
// fp16 hi/lo fragment buffer for GEMM1 -> GEMM2 intermediate (K=512 operand)
__device__ uint4 g_a16b[(size_t)(MPAD_N / 16) * (FDIM / 16) * 64];
// B16 weights
__device__ uint4 g_w16[393216];
// CSR (by destination)
__device__ int g_deg[NN];
__device__ int g_fill[NN];
__device__ int g_rs[NN + 1];
__device__ int g_bsum[512];
__device__ int g_srcs[EE];
__device__ int g_attrs[EE];

__device__ __forceinline__ float softplus_f(float x) {
    return fmaxf(x, 0.0f) + log1pf(expf(-fabsf(x)));
}

__device__ __forceinline__ void red_add_f32(float* p, float v) {
    asm volatile("red.global.add.f32 [%0], %1;" :: "l"(p), "f"(v) : "memory");
}
__device__ __forceinline__ void red_add_v4(float* p, float x, float y, float z, float w) {
    asm volatile("red.global.add.v4.f32 [%0], {%1,%2,%3,%4};"
                 :: "l"(p), "f"(x), "f"(y), "f"(z), "f"(w) : "memory");
}

// ---------------- fp16 split helpers ----------------
__device__ __forceinline__ void packhl(float x, float y, uint32_t& hi, uint32_t& lo) {
    __half2 h = __floats2half2_rn(x, y);
    float2 hf = __half22float2(h);
    __half2 l = __floats2half2_rn(x - hf.x, y - hf.y);
    hi = *reinterpret_cast<uint32_t*>(&h);
    lo = *reinterpret_cast<uint32_t*>(&l);
}

__device__ __forceinline__ void mma16(float* c, const uint32_t* a, uint32_t b0, uint32_t b1) {
    asm volatile(
        "mma.sync.aligned.m16n8k16.row.col.f32.f16.f16.f32 "
        "{%0,%1,%2,%3},{%4,%5,%6,%7},{%8,%9},{%0,%1,%2,%3};"
        : "+f"(c[0]), "+f"(c[1]), "+f"(c[2]), "+f"(c[3])
        : "r"(a[0]), "r"(a[1]), "r"(a[2]), "r"(a[3]), "r"(b0), "r"(b1));
}

__device__ __forceinline__ void cpa16(void* dst, const void* src, int srcBytes) {
    uint32_t d = (uint32_t)__cvta_generic_to_shared(dst);
    asm volatile("cp.async.cg.shared.global [%0], [%1], 16, %2;"
                 :: "r"(d), "l"(src), "r"(srcBytes) : "memory");
}
__device__ __forceinline__ void cpa16f(void* dst, const void* src) {
    uint32_t d = (uint32_t)__cvta_generic_to_shared(dst);
    asm volatile("cp.async.cg.shared.global [%0], [%1], 16;" :: "r"(d), "l"(src) : "memory");
}
__device__ __forceinline__ void cp_commit() {
    asm volatile("cp.async.commit_group;" ::: "memory");
}
__device__ __forceinline__ void cp_wait0() {
    asm volatile("cp.async.wait_group 0;" ::: "memory");
}

// ---------------- CSR build ----------------
__global__ void csr_zero(int* deg, int* fill) {
    int i = blockIdx.x * blockDim.x + threadIdx.x;
    if (i < NN) { deg[i] = 0; fill[i] = 0; }
}
__global__ void csr_count(const int* __restrict__ edge_index, int* __restrict__ deg) {
    int e = blockIdx.x * blockDim.x + threadIdx.x;
    if (e < EE) atomicAdd(&deg[edge_index[EE + e]], 1);
}
__global__ void csr_scan1(const int* __restrict__ deg, int* __restrict__ rs,
                          int* __restrict__ bsum) {
    __shared__ int sm[256];
    int tid = threadIdx.x;
    int i = blockIdx.x * 256 + tid;
    int v = (i < NN) ? deg[i] : 0;
    sm[tid] = v;
    __syncthreads();
#pragma unroll
    for (int o = 1; o < 256; o <<= 1) {
        int t = (tid >= o) ? sm[tid - o] : 0;
        __syncthreads();
        if (tid >= o) sm[tid] += t;
        __syncthreads();
    }
    if (i < NN) rs[i] = sm[tid] - v;
    if (tid == 255) bsum[blockIdx.x] = sm[255];
}
__global__ void csr_scan2(int* __restrict__ bsum) {
    __shared__ int sm[512];
    int tid = threadIdx.x;
    int v = (tid < NB_SCAN) ? bsum[tid] : 0;
    sm[tid] = v;
    __syncthreads();
#pragma unroll
    for (int o = 1; o < 512; o <<= 1) {
        int t = (tid >= o) ? sm[tid - o] : 0;
        __syncthreads();
        if (tid >= o) sm[tid] += t;
        __syncthreads();
    }
    if (tid < NB_SCAN) bsum[tid] = sm[tid] - v;  // exclusive
}
__global__ void csr_scan3(int* __restrict__ rs, const int* __restrict__ bsum) {
    int i = blockIdx.x * 256 + threadIdx.x;
    if (i < NN) rs[i] += bsum[blockIdx.x];
    if (i == 0) rs[NN] = EE;
}
__global__ void csr_place(const int* __restrict__ edge_index,
                          const int* __restrict__ edge_attr,
                          const int* __restrict__ rs, int* __restrict__ fill,
                          int* __restrict__ srcs, int* __restrict__ attrs) {
    int e = blockIdx.x * blockDim.x + threadIdx.x;
    if (e >= EE) return;
    int d = edge_index[EE + e];
    int p = rs[d] + atomicAdd(&fill[d], 1);
    srcs[p] = edge_index[e];
    attrs[p] = edge_attr[e];
}

// ---------------- gather: agg[i] = h[i]+emb_self + sum_in (h[src]+emb[attr]) ---------
__global__ void gather_edges_kernel(const float* __restrict__ h,
                                    const int* __restrict__ srcs,
                                    const int* __restrict__ attrs,
                                    const int* __restrict__ rs,
                                    const float* __restrict__ emb,
                                    float* __restrict__ agg) {
    int node = blockIdx.x * (blockDim.x >> 5) + (threadIdx.x >> 5);
    if (node >= NN) return;
    int lane = threadIdx.x & 31;
    int c0 = lane * 4, c1 = c0 + 128;
    const float* hn = h + (size_t)node * DD;
    const float* es = emb + (size_t)(NUM_BOND_C - 1) * DD;
    float4 v0 = *(const float4*)(hn + c0);
    float4 v1 = *(const float4*)(hn + c1);
    float4 e0 = *(const float4*)(es + c0);
    float4 e1 = *(const float4*)(es + c1);
    float4 a0 = make_float4(v0.x + e0.x, v0.y + e0.y, v0.z + e0.z, v0.w + e0.w);
    float4 a1 = make_float4(v1.x + e1.x, v1.y + e1.y, v1.z + e1.z, v1.w + e1.w);
    int p0 = rs[node], p1 = rs[node + 1];
    for (int p = p0; p < p1; p++) {
        int s = srcs[p], a = attrs[p];
        const float* hs = h + (size_t)s * DD;
        const float* eb = emb + (size_t)a * DD;
        float4 h0 = *(const float4*)(hs + c0);
        float4 h1 = *(const float4*)(hs + c1);
        float4 b0 = *(const float4*)(eb + c0);
        float4 b1 = *(const float4*)(eb + c1);
        a0.x += h0.x + b0.x; a0.y += h0.y + b0.y; a0.z += h0.z + b0.z; a0.w += h0.w + b0.w;
        a1.x += h1.x + b1.x; a1.y += h1.y + b1.y; a1.z += h1.z + b1.z; a1.w += h1.w + b1.w;
    }
    float* ag = agg + (size_t)node * DD;
    *(float4*)(ag + c0) = a0;
    *(float4*)(ag + c1) = a1;
}

// ---------------- B16 converter ----------------
__global__ void conv_b16(const float* __restrict__ W, uint4* __restrict__ dst, int K, int N) {
    int Q = K >> 4;
    int wid = blockIdx.x * (blockDim.x >> 5) + (threadIdx.x >> 5);
    int nch = (N >> 3) * Q;
    if (wid >= nch) return;
    int bn = wid / Q, q = wid - bn * Q;
    int lane = threadIdx.x & 31, g = lane >> 2, t = lane & 3;
    int n = bn * 8 + g;
    int k0 = q * 16 + 2 * t, k1 = k0 + 8;
    uint4 v;
    uint32_t l0, l1;
    packhl(W[(size_t)k0 * N + n], W[(size_t)(k0 + 1) * N + n], v.x, l0);
    packhl(W[(size_t)k1 * N + n], W[(size_t)(k1 + 1) * N + n], v.y, l1);
    v.z = l0;
    v.w = l1;
    dst[(size_t)wid * 32 + lane] = v;
}

// ---------------- fp16x3 tensor-core GEMM ----------------
#define GEMM_SMEM_BYTES 65536

__global__ __launch_bounds__(256, 2)
void gemm_f16(const uint4* __restrict__ A16, const float* __restrict__ Afp,
              const uint4* __restrict__ B16, const float* __restrict__ bias,
              float* __restrict__ C, uint4* __restrict__ O16, int M, int Qa, int Nc,
              int act, float* __restrict__ stat, int Qout) {
    extern __shared__ uint4 sm4[];
    const int tid = threadIdx.x, lane = tid & 31, w = tid >> 5;
    const int g = lane >> 2, t = lane & 3;
    const int wm = (w >> 1) * 32, wn = (w & 1) * 64;
    const int brow = blockIdx.y * 128, bcol = blockIdx.x * 128;
    const bool a32 = (Afp != nullptr);
    const int K = Qa << 4;

    const uint4* asrc[4];
    uint4* adst[4];
    const uint4* bsrc[4];
    uint4* bdst[4];
#pragma unroll
    for (int j = 0; j < 4; j++) {
        int u = tid + j * 256;
        {
            int chunk = u >> 6, wd = u & 63;
            int bm = chunk >> 1, ql = chunk & 1;
            asrc[j] = A16 + ((size_t)((brow >> 4) + bm) * Qa + ql) * 64 + wd;
            adst[j] = sm4 + (ql * 8 + bm) * 64 + wd;
        }
        {
            int chunk = u >> 5, wd = u & 31;
            int bn = chunk >> 1, ql = chunk & 1;
            bsrc[j] = B16 + ((size_t)((bcol >> 3) + bn) * Qa + ql) * 32 + wd;
            bdst[j] = sm4 + 1024 + (ql * 16 + bn) * 32 + wd;
        }
    }

    const int ac = tid & 7;
    const int ar0 = tid >> 3;
    const int acsw = ac ^ (ar0 & 7);
    const float* asrc32[4];
    uint4* adst32[4];
    int aokb[4];
    if (a32) {
#pragma unroll
        for (int j = 0; j < 4; j++) {
            int row = ar0 + 32 * j;
            int rowg = brow + row;
            aokb[j] = (rowg < M) ? 16 : 0;
            asrc32[j] = Afp + (size_t)((rowg < M) ? rowg : 0) * K + ac * 4;
            adst32[j] = sm4 + row * 8 + acsw;
        }
    }

    float acc[2][8][4];
#pragma unroll
    for (int mt = 0; mt < 2; mt++)
#pragma unroll
        for (int nt = 0; nt < 8; nt++)
#pragma unroll
            for (int q = 0; q < 4; q++) acc[mt][nt][q] = 0.0f;

    const int S = Qa >> 1;

    if (a32) {
#pragma unroll
        for (int j = 0; j < 4; j++) cpa16(adst32[j], asrc32[j], aokb[j]);
    } else {
#pragma unroll
        for (int j = 0; j < 4; j++) cpa16f(adst[j], asrc[j]);
    }
#pragma unroll
    for (int j = 0; j < 4; j++) cpa16f(bdst[j], bsrc[j]);
    cp_commit();

    for (int s = 0; s < S; s++) {
        const int st = s & 1;
        cp_wait0();
        __syncthreads();
        if (s + 1 < S) {
            const int st2 = st ^ 1;
            if (a32) {
#pragma unroll
                for (int j = 0; j < 4; j++)
                    cpa16(adst32[j] + st2 * 2048, asrc32[j] + (size_t)(s + 1) * 32, aokb[j]);
            } else {
#pragma unroll
                for (int j = 0; j < 4; j++)
                    cpa16f(adst[j] + st2 * 2048, asrc[j] + (size_t)(s + 1) * 128);
            }
#pragma unroll
            for (int j = 0; j < 4; j++)
                cpa16f(bdst[j] + st2 * 2048, bsrc[j] + (size_t)(s + 1) * 64);
        }
        cp_commit();

#pragma unroll
        for (int ql = 0; ql < 2; ql++) {
            uint4 ah[2], al[2];
            if (a32) {
                const float* As = (const float*)(sm4 + st * 2048);
#pragma unroll
                for (int mt = 0; mt < 2; mt++) {
                    const int r = wm + mt * 16 + g;
                    const int rb = r * 32;
                    const int c1 = ((ql * 4) | (t >> 1)) ^ g;
                    const int c2 = c1 ^ 2;
                    const int hw = (t & 1) * 2;
                    float2 f0 = *(const float2*)(As + rb + c1 * 4 + hw);
                    float2 f1 = *(const float2*)(As + rb + 256 + c1 * 4 + hw);
                    float2 f2 = *(const float2*)(As + rb + c2 * 4 + hw);
                    float2 f3 = *(const float2*)(As + rb + 256 + c2 * 4 + hw);
                    packhl(f0.x, f0.y, ah[mt].x, al[mt].x);
                    packhl(f1.x, f1.y, ah[mt].y, al[mt].y);
                    packhl(f2.x, f2.y, ah[mt].z, al[mt].z);
                    packhl(f3.x, f3.y, ah[mt].w, al[mt].w);
                }
            } else {
#pragma unroll
                for (int mt = 0; mt < 2; mt++) {
                    const uint4* ap = sm4 + st * 2048 + (ql * 8 + (wm >> 4) + mt) * 64;
                    ah[mt] = ap[lane];
                    al[mt] = ap[32 + lane];
                }
            }
#pragma unroll
            for (int nt = 0; nt < 8; nt++) {
                uint4 bv = sm4[st * 2048 + 1024 + (ql * 16 + (wn >> 3) + nt) * 32 + lane];
#pragma unroll
                for (int mt = 0; mt < 2; mt++) {
                    mma16(acc[mt][nt], (const uint32_t*)&ah[mt], bv.x, bv.y);
                    mma16(acc[mt][nt], (const uint32_t*)&ah[mt], bv.z, bv.w);
                    mma16(acc[mt][nt], (const uint32_t*)&al[mt], bv.x, bv.y);
                }
            }
        }
    }

    const bool do_stats = (stat != nullptr);
    float csum[16], csq[16];
    if (do_stats) {
#pragma unroll
        for (int i = 0; i < 16; i++) { csum[i] = 0.f; csq[i] = 0.f; }
    }

#pragma unroll
    for (int mt = 0; mt < 2; mt++) {
        const int r0 = brow + wm + mt * 16 + g;
        const int r1 = r0 + 8;
#pragma unroll
        for (int j = 0; j < 4; j++) {
            float v[2][4];
#pragma unroll
            for (int e = 0; e < 2; e++) {
                const int nt = j * 2 + e;
                const int col = bcol + wn + nt * 8 + t * 2;
                const float b0 = bias[col];
                const float b1 = bias[col + 1];
                float x0 = acc[mt][nt][0] + b0;
                float x1 = acc[mt][nt][1] + b1;
                float x2 = acc[mt][nt][2] + b0;
                float x3 = acc[mt][nt][3] + b1;
                if (act) {
                    x0 = softplus_f(x0); x1 = softplus_f(x1);
                    x2 = softplus_f(x2); x3 = softplus_f(x3);
                }
                if (r0 >= M) { x0 = 0.f; x1 = 0.f; }
                if (r1 >= M) { x2 = 0.f; x3 = 0.f; }
                v[e][0] = x0; v[e][1] = x1; v[e][2] = x2; v[e][3] = x3;
                if (C) {
                    if (r0 < M) *(float2*)&C[(size_t)r0 * Nc + col] = make_float2(x0, x1);
                    if (r1 < M) *(float2*)&C[(size_t)r1 * Nc + col] = make_float2(x2, x3);
                }
                if (do_stats) {
                    csum[nt * 2] += x0 + x2;
                    csq[nt * 2] += x0 * x0 + x2 * x2;
                    csum[nt * 2 + 1] += x1 + x3;
                    csq[nt * 2 + 1] += x1 * x1 + x3 * x3;
                }
            }
            if (O16) {
                uint4 hi, lo;
                packhl(v[0][0], v[0][1], hi.x, lo.x);
                packhl(v[0][2], v[0][3], hi.y, lo.y);
                packhl(v[1][0], v[1][1], hi.z, lo.z);
                packhl(v[1][2], v[1][3], hi.w, lo.w);
                size_t chunk = (size_t)((brow + wm + mt * 16) >> 4) * Qout +
                               ((bcol + wn) >> 4) + j;
                O16[chunk * 64 + lane] = hi;
                O16[chunk * 64 + 32 + lane] = lo;
            }
        }
    }

    if (do_stats) {
#pragma unroll
        for (int i = 0; i < 16; i++) {
            float sv = csum[i], qv = csq[i];
            sv += __shfl_xor_sync(0xffffffffu, sv, 4);
            sv += __shfl_xor_sync(0xffffffffu, sv, 8);
            sv += __shfl_xor_sync(0xffffffffu, sv, 16);
            qv += __shfl_xor_sync(0xffffffffu, qv, 4);
            qv += __shfl_xor_sync(0xffffffffu, qv, 8);
            qv += __shfl_xor_sync(0xffffffffu, qv, 16);
            if (g == 0) {
                const int col = bcol + wn + (i >> 1) * 8 + t * 2 + (i & 1);
                red_add_f32(&stat[col], sv);
                red_add_f32(&stat[Nc + col], qv);
            }
        }
    }
}

// ---------------- non-GEMM kernels ----------------
__global__ void init_h_kernel(const int* __restrict__ atomics,
                              const float* __restrict__ pos,
                              const float* __restrict__ emb1,
                              const float* __restrict__ w2,
                              const float* __restrict__ b2,
                              float* __restrict__ h) {
    size_t idx = (size_t)blockIdx.x * blockDim.x + threadIdx.x;
    if (idx >= (size_t)NN * DD) return;
    int i = (int)(idx / DD);
    int d = (int)(idx & (DD - 1));
    float p0 = pos[i * 3 + 0], p1 = pos[i * 3 + 1], p2 = pos[i * 3 + 2];
    float v = emb1[(size_t)atomics[i] * DD + d];
    v += p0 * w2[d] + p1 * w2[DD + d] + p2 * w2[2 * DD + d] + b2[d];
    h[idx] = v;
}

__global__ void zero_kernel(float* __restrict__ p, size_t n) {
    size_t idx = (size_t)blockIdx.x * blockDim.x + threadIdx.x;
    if (idx < n) p[idx] = 0.0f;
}

__global__ void bn_finalize_kernel(const float* __restrict__ stat,
                                   const float* __restrict__ gamma,
                                   const float* __restrict__ beta,
                                   float* __restrict__ ab) {
    int d = threadIdx.x;
    float mean = stat[d] * (1.0f / NN);
    float var = stat[DD + d] * (1.0f / NN) - mean * mean;
    float inv = rsqrtf(var + BN_EPS);
    float a = gamma[d] * inv;
    ab[d] = a;
    ab[DD + d] = beta[d] - mean * a;
}

__global__ void bn_apply_kernel(float* __restrict__ h, const float* __restrict__ ab,
                                int act) {
    size_t idx = (size_t)blockIdx.x * blockDim.x + threadIdx.x;
    if (idx >= (size_t)NN * DD / 4) return;
    int d4 = (int)(idx & (DD / 4 - 1)) * 4;
    float4 v = *((float4*)h + idx);
    float4 a = *(const float4*)(ab + d4);
    float4 b = *(const float4*)(ab + DD + d4);
    v.x = v.x * a.x + b.x;
    v.y = v.y * a.y + b.y;
    v.z = v.z * a.z + b.z;
    v.w = v.w * a.w + b.w;
    if (act) {
        v.x = softplus_f(v.x);
        v.y = softplus_f(v.y);
        v.z = softplus_f(v.z);
        v.w = softplus_f(v.w);
    }
    *((float4*)h + idx) = v;
}

__global__ void pool_count_kernel(const int* __restrict__ batch, float* __restrict__ cnt) {
    int i = blockIdx.x * blockDim.x + threadIdx.x;
    if (i >= NN) return;
    atomicAdd(&cnt[batch[i]], 1.0f);
}

// pool raw h (256 channels): sorted batch, 8-node runs per thread
__global__ void pool_sum_h_kernel(const float* __restrict__ h,
                                  const int* __restrict__ batch,
                                  float* __restrict__ ssum) {
    size_t idx = (size_t)blockIdx.x * blockDim.x + threadIdx.x;
    const int CH = DD / 4;
    const size_t nchunks = (NN + 7) / 8;
    if (idx >= nchunks * CH) return;
    int f4 = (int)(idx & (CH - 1)) * 4;
    int i0 = (int)(idx / CH) * 8;
    int cur = batch[i0];
    float4 acc = make_float4(0.f, 0.f, 0.f, 0.f);
#pragma unroll
    for (int r = 0; r < 8; r++) {
        int i = i0 + r;
        if (i >= NN) break;
        int b = batch[i];
        if (b != cur) {
            red_add_v4(&ssum[(size_t)cur * DD + f4], acc.x, acc.y, acc.z, acc.w);
            acc = make_float4(0.f, 0.f, 0.f, 0.f);
            cur = b;
        }
        float4 v = *(const float4*)(h + (size_t)i * DD + f4);
        acc.x += v.x; acc.y += v.y; acc.z += v.z; acc.w += v.w;
    }
    red_add_v4(&ssum[(size_t)cur * DD + f4], acc.x, acc.y, acc.z, acc.w);
}

// pm[g,c] = (ssum[g,c]/max(cnt,1)) * ab_a[c] + ab_b[c]   (BN affine on pooled mean)
__global__ void pm_kernel(const float* __restrict__ ssum, const float* __restrict__ cnt,
                          const float* __restrict__ ab, float* __restrict__ pm) {
    size_t idx = (size_t)blockIdx.x * blockDim.x + threadIdx.x;
    if (idx >= (size_t)GG * DD) return;
    int g = (int)(idx / DD);
    int c = (int)(idx & (DD - 1));
    float m = ssum[idx] / fmaxf(cnt[g], 1.0f);
    pm[idx] = m * ab[c] + ab[DD + c];
}

__global__ void head_out_kernel(const float* __restrict__ hid, const float* __restrict__ w2,
                                const float* __restrict__ b2, float* __restrict__ out) {
    int g = blockIdx.x * (blockDim.x >> 5) + (threadIdx.x >> 5);
    if (g >= GG) return;
    int lane = threadIdx.x & 31;
    const float* hr = hid + (size_t)g * (FDIM / 2);
    float s = 0.f;
#pragma unroll
    for (int k = lane; k < FDIM / 2; k += 32) s += hr[k] * w2[k];
#pragma unroll
    for (int o = 16; o; o >>= 1) s += __shfl_down_sync(0xffffffffu, s, o);
    if (lane == 0) out[g] = s + b2[0];
}

// ---------------- host launch ----------------
static inline void launch_gemm(const uint4* A16, const float* Afp, const uint4* B16,
                               const float* bias, float* C, uint4* O16, int M, int Mpad,
                               int Qa, int Nc, int act, float* stat, int Qout) {
    dim3 grid(Nc / 128, Mpad / 128);
    gemm_f16<<<grid, 256, GEMM_SMEM_BYTES>>>(A16, Afp, B16, bias, C, O16, M, Qa, Nc, act,
                                             stat, Qout);
}

extern "C" void kernel_launch(void* const* d_in, const int* in_sizes, int n_in,
                              void* d_out, int out_size) {
    const int* atomics = (const int*)d_in[0];
    const float* pos = (const float*)d_in[1];
    const int* edge_index = (const int*)d_in[2];
    const int* edge_attr = (const int*)d_in[3];
    const int* batch = (const int*)d_in[4];
    const float* x_emb1 = (const float*)d_in[5];
    const float* x_emb2_w = (const float*)d_in[6];
    const float* x_emb2_b = (const float*)d_in[7];
    const float* edge_emb = (const float*)d_in[8];
    const float* mlp_w1 = (const float*)d_in[9];
    const float* mlp_b1 = (const float*)d_in[10];
    const float* mlp_w2 = (const float*)d_in[11];
    const float* mlp_b2 = (const float*)d_in[12];
    const float* bn_gamma = (const float*)d_in[13];
    const float* bn_beta = (const float*)d_in[14];
    const float* feat_w = (const float*)d_in[15];
    const float* feat_b = (const float*)d_in[16];
    const float* head_w1 = (const float*)d_in[17];
    const float* head_b1 = (const float*)d_in[18];
    const float* head_w2 = (const float*)d_in[19];
    const float* head_b2 = (const float*)d_in[20];
    float* out = (float*)d_out;

    float *h, *agg, *stat, *ab, *ssum, *cnt, *pm, *gfeat, *hid;
    uint4 *a16b, *w16;
    int *deg, *fill, *rs, *bsum, *srcs, *attrs;
    cudaGetSymbolAddress((void**)&h, g_h);
    cudaGetSymbolAddress((void**)&agg, g_agg);
    cudaGetSymbolAddress((void**)&stat, g_stat);
    cudaGetSymbolAddress((void**)&ab, g_ab);
    cudaGetSymbolAddress((void**)&ssum, g_ssum);
    cudaGetSymbolAddress((void**)&cnt, g_cnt);
    cudaGetSymbolAddress((void**)&pm, g_pm);
    cudaGetSymbolAddress((void**)&gfeat, g_gfeat);
    cudaGetSymbolAddress((void**)&hid, g_hid);
    cudaGetSymbolAddress((void**)&a16b, g_a16b);
    cudaGetSymbolAddress((void**)&w16, g_w16);
    cudaGetSymbolAddress((void**)&deg, g_deg);
    cudaGetSymbolAddress((void**)&fill, g_fill);
    cudaGetSymbolAddress((void**)&rs, g_rs);
    cudaGetSymbolAddress((void**)&bsum, g_bsum);
    cudaGetSymbolAddress((void**)&srcs, g_srcs);
    cudaGetSymbolAddress((void**)&attrs, g_attrs);

    cudaFuncSetAttribute(gemm_f16, cudaFuncAttributeMaxDynamicSharedMemorySize,
                         GEMM_SMEM_BYTES);

    const size_t ND = (size_t)NN * DD;
    const size_t ND4 = ND / 4;
    const int EL = 256;

    // ---- CSR build ----
    csr_zero<<<(NN + EL - 1) / EL, EL>>>(deg, fill);
    csr_count<<<(EE + EL - 1) / EL, EL>>>(edge_index, deg);
    csr_scan1<<<NB_SCAN, 256>>>(deg, rs, bsum);
    csr_scan2<<<1, 512>>>(bsum);
    csr_scan3<<<NB_SCAN, 256>>>(rs, bsum);
    csr_place<<<(EE + EL - 1) / EL, EL>>>(edge_index, edge_attr, rs, fill, srcs, attrs);

    // ---- B16 prep ----
    for (int l = 0; l < LL; l++) {
        conv_b16<<<128, 256>>>(mlp_w1 + (size_t)l * DD * 2 * DD, w16 + l * 32768, DD, 2 * DD);
        conv_b16<<<128, 256>>>(mlp_w2 + (size_t)l * 2 * DD * DD, w16 + 163840 + l * 32768,
                               2 * DD, DD);
    }
    conv_b16<<<128, 256>>>(feat_w, w16 + 327680, DD, FDIM);
    conv_b16<<<128, 256>>>(head_w1, w16 + 360448, FDIM, FDIM / 2);

    init_h_kernel<<<(unsigned)((ND + EL - 1) / EL), EL>>>(atomics, pos, x_emb1, x_emb2_w,
                                                          x_emb2_b, h);

    for (int l = 0; l < LL; l++) {
        const float* emb_l = edge_emb + (size_t)l * NUM_BOND_C * DD;

        gather_edges_kernel<<<(NN + 7) / 8, 256>>>(h, srcs, attrs, rs, emb_l, agg);

        launch_gemm(nullptr, agg, w16 + l * 32768, mlp_b1 + (size_t)l * 2 * DD, nullptr,
                    a16b, NN, MPAD_N, DD / 16, 2 * DD, 1, nullptr, FDIM / 16);

        zero_kernel<<<1, 512>>>(stat, 2 * DD);
        launch_gemm(a16b, nullptr, w16 + 163840 + l * 32768, mlp_b2 + (size_t)l * DD, h,
                    nullptr, NN, MPAD_N, FDIM / 16, DD, 0, stat, 1);

        bn_finalize_kernel<<<1, 256>>>(stat, bn_gamma + (size_t)l * DD,
                                       bn_beta + (size_t)l * DD, ab);

        if (l < LL - 1) {
            bn_apply_kernel<<<(unsigned)((ND4 + EL - 1) / EL), EL>>>(h, ab, 1);
        }
        // l == LL-1: BN affine commutes with mean pooling; applied on pooled means.
    }

    // ---- pool raw h, then apply BN affine on the means ----
    zero_kernel<<<(unsigned)(((size_t)GG * DD + EL - 1) / EL), EL>>>(ssum, (size_t)GG * DD);
    zero_kernel<<<(GG + EL - 1) / EL, EL>>>(cnt, GG);
    pool_count_kernel<<<(NN + EL - 1) / EL, EL>>>(batch, cnt);
    {
        size_t total = ((NN + 7) / 8) * (size_t)(DD / 4);
        pool_sum_h_kernel<<<(unsigned)((total + EL - 1) / EL), EL>>>(h, batch, ssum);
    }
    pm_kernel<<<(unsigned)(((size_t)GG * DD + EL - 1) / EL), EL>>>(ssum, cnt, ab, pm);

    // gfeat = pm @ feat_w + feat_b   [G,512]  (pool/feat commute)
    launch_gemm(nullptr, pm, w16 + 327680, feat_b, gfeat, nullptr, GG, MPAD_G, DD / 16,
                FDIM, 0, nullptr, 1);

    // head: hid = softplus(gfeat @ head_w1 + head_b1)
    launch_gemm(nullptr, gfeat, w16 + 360448, head_b1, hid, nullptr, GG, MPAD_G, FDIM / 16,
                FDIM / 2, 1, nullptr, 1);
    head_out_kernel<<<(GG + 7) / 8, 256>>>(hid, head_w2, head_b2, out);
}